// round 2
// baseline (speedup 1.0000x reference)
#include <cuda_runtime.h>
#include <cstdint>

// Problem constants (from reference): B=2, S_LEN=2048 -> S=4096 tokens
#define S_TOK 4096
#define DIM   2048
#define NE    8
#define FF    5504
#define CAP   1024   // max(int(2*S/E*1.0), 4)

// ---------------- scratch (device globals; no dynamic allocation allowed) ---
__device__ float g_logits[S_TOK * NE];
__device__ int   g_idx1[S_TOK];
__device__ int   g_idx2[S_TOK];
__device__ float g_g1[S_TOK];
__device__ float g_g2[S_TOK];
__device__ int   g_slot1[S_TOK];
__device__ int   g_slot2[S_TOK];
__device__ int   g_tok4slot[NE * CAP];
__device__ int   g_count1[NE];
__device__ float g_me[NE];
__device__ float g_laux;
__device__ float g_xe[(size_t)NE * CAP * DIM];   //  64 MB
__device__ float g_t3[(size_t)NE * CAP * FF];    // 176 MB
__device__ float g_h [(size_t)NE * CAP * FF];    // 176 MB
__device__ float g_eo[(size_t)NE * CAP * DIM];   //  64 MB

// ---------------- packed f32x2 helpers (Blackwell FFMA2 path) --------------
__device__ __forceinline__ unsigned long long pack2(float lo, float hi) {
    unsigned long long r;
    asm("mov.b64 %0, {%1, %2};" : "=l"(r) : "f"(lo), "f"(hi));
    return r;
}
__device__ __forceinline__ void fma2(unsigned long long& d,
                                     unsigned long long a,
                                     unsigned long long b) {
    asm("fma.rn.f32x2 %0, %1, %2, %0;" : "+l"(d) : "l"(a), "l"(b));
}
__device__ __forceinline__ float2 unpack2(unsigned long long v) {
    float2 f;
    asm("mov.b64 {%0, %1}, %2;" : "=f"(f.x), "=f"(f.y) : "l"(v));
    return f;
}

// ---------------- init: reset per-call mutable scratch ----------------------
__global__ void k_init() {
    int i = blockIdx.x * blockDim.x + threadIdx.x;
    if (i < NE * CAP) g_tok4slot[i] = -1;
    if (i < NE) g_me[i] = 0.f;
}

// ---------------- gating logits: x[S,D] @ wg[D,E] ---------------------------
__global__ void k_logits(const float* __restrict__ x, const float* __restrict__ wg) {
    int s = blockIdx.x;
    float acc[NE];
#pragma unroll
    for (int e = 0; e < NE; e++) acc[e] = 0.f;
    const float* xr = x + (size_t)s * DIM;
    for (int j = threadIdx.x; j < DIM; j += blockDim.x) {
        float xv = xr[j];
        float4 w0 = *(const float4*)(wg + (size_t)j * NE);
        float4 w1v = *(const float4*)(wg + (size_t)j * NE + 4);
        acc[0] += xv * w0.x;  acc[1] += xv * w0.y;
        acc[2] += xv * w0.z;  acc[3] += xv * w0.w;
        acc[4] += xv * w1v.x; acc[5] += xv * w1v.y;
        acc[6] += xv * w1v.z; acc[7] += xv * w1v.w;
    }
#pragma unroll
    for (int off = 16; off; off >>= 1)
#pragma unroll
        for (int e = 0; e < NE; e++)
            acc[e] += __shfl_down_sync(0xffffffffu, acc[e], off);
    __shared__ float red[4][NE];
    int lane = threadIdx.x & 31, wp = threadIdx.x >> 5;
    if (lane == 0)
#pragma unroll
        for (int e = 0; e < NE; e++) red[wp][e] = acc[e];
    __syncthreads();
    if (threadIdx.x < NE) {
        float v = red[0][threadIdx.x] + red[1][threadIdx.x] +
                  red[2][threadIdx.x] + red[3][threadIdx.x];
        g_logits[(size_t)s * NE + threadIdx.x] = v;
    }
}

// ---------------- per-token softmax + top-2 ---------------------------------
__global__ void k_top2() {
    __shared__ float sme[NE];
    if (threadIdx.x < NE) sme[threadIdx.x] = 0.f;
    __syncthreads();
    int s = blockIdx.x * blockDim.x + threadIdx.x;
    float l[NE];
    float4 a = *(const float4*)(g_logits + (size_t)s * NE);
    float4 b = *(const float4*)(g_logits + (size_t)s * NE + 4);
    l[0] = a.x; l[1] = a.y; l[2] = a.z; l[3] = a.w;
    l[4] = b.x; l[5] = b.y; l[6] = b.z; l[7] = b.w;
    float mx = l[0];
#pragma unroll
    for (int e = 1; e < NE; e++) mx = fmaxf(mx, l[e]);
    float g[NE]; float sum = 0.f;
#pragma unroll
    for (int e = 0; e < NE; e++) { g[e] = __expf(l[e] - mx); sum += g[e]; }
    float inv = 1.f / sum;
    int i1 = 0; float b1 = l[0];
#pragma unroll
    for (int e = 1; e < NE; e++) if (l[e] > b1) { b1 = l[e]; i1 = e; }
    int i2 = 0; float b2 = -3.0e38f;
#pragma unroll
    for (int e = 0; e < NE; e++) if (e != i1 && l[e] > b2) { b2 = l[e]; i2 = e; }
    g_idx1[s] = i1;  g_idx2[s] = i2;
    g_g1[s] = g[i1] * inv;  g_g2[s] = g[i2] * inv;
#pragma unroll
    for (int e = 0; e < NE; e++) atomicAdd(&sme[e], g[e] * inv);
    __syncthreads();
    if (threadIdx.x < NE) atomicAdd(&g_me[threadIdx.x], sme[threadIdx.x]);
}

// ---------------- capacity scan: 1 warp per expert, ballot prefix-sum -------
__global__ void k_scan() {
    int lane = threadIdx.x & 31;
    int e = threadIdx.x >> 5;
    unsigned lmask = (1u << lane) - 1u;
    if (e < NE) {
        int c1 = 0;
        for (int s0 = 0; s0 < S_TOK; s0 += 32) {
            int s = s0 + lane;
            int m = (g_idx1[s] == e);
            unsigned bal = __ballot_sync(0xffffffffu, m);
            if (m) {
                int pos = c1 + __popc(bal & lmask);
                if (pos < CAP) { g_slot1[s] = pos; g_tok4slot[e * CAP + pos] = s; }
                else g_slot1[s] = -1;
            }
            c1 += __popc(bal);
        }
        if (lane == 0) g_count1[e] = c1;   // pre-drop count = exp_counts
        int c2 = c1;                        // loc2 offset uses pre-drop sum(mask1)
        for (int s0 = 0; s0 < S_TOK; s0 += 32) {
            int s = s0 + lane;
            int m = (g_idx2[s] == e);
            unsigned bal = __ballot_sync(0xffffffffu, m);
            if (m) {
                int pos = c2 + __popc(bal & lmask);
                if (pos < CAP) { g_slot2[s] = pos; g_tok4slot[e * CAP + pos] = s; }
                else g_slot2[s] = -1;
            }
            c2 += __popc(bal);
        }
    }
    __syncthreads();
    if (threadIdx.x == 0) {
        // l_aux = mean_e(me*ce) * E^2 = E * sum_e(me*ce)
        float acc = 0.f;
        for (int i = 0; i < NE; i++)
            acc += (g_me[i] / (float)S_TOK) * ((float)g_count1[i] / (float)S_TOK);
        g_laux = acc * (float)NE;
    }
}

// ---------------- dispatch: gather tokens into xe[E,C,D] --------------------
__global__ void k_dispatch(const float* __restrict__ x) {
    int slot = blockIdx.x;                 // 0..E*CAP-1
    int s = g_tok4slot[slot];
    float4* dst = (float4*)(g_xe + (size_t)slot * DIM);
    if (s >= 0) {
        const float4* src = (const float4*)(x + (size_t)s * DIM);
        for (int j = threadIdx.x; j < DIM / 4; j += blockDim.x) dst[j] = src[j];
    } else {
        float4 z = make_float4(0.f, 0.f, 0.f, 0.f);
        for (int j = threadIdx.x; j < DIM / 4; j += blockDim.x) dst[j] = z;
    }
}

// ---------------- grouped SGEMM (per-expert via blockIdx.z), f32x2 mainloop -
// C[e] = A[e] @ B[e];  EPI==1: C = silu(acc) * Aux  (for h = silu(xe@w1)*t3)
#define BM 128
#define BN 128
#define BK 16

template <int EPI>
__global__ void __launch_bounds__(256, 2)
sgemm(const float* __restrict__ Ag, const float* __restrict__ Bg,
      float* __restrict__ Cg, const float* __restrict__ Auxg,
      int M, int N, int K) {
    __shared__ float As[BK][BM];
    __shared__ float Bs[BK][BN];
    const int tid = threadIdx.x;
    const size_t eoffC = (size_t)blockIdx.z * M * N;
    const float* A = Ag + (size_t)blockIdx.z * M * K;
    const float* B = Bg + (size_t)blockIdx.z * K * N;
    float* C = Cg + eoffC;

    const int row0 = blockIdx.y * BM;
    const int col0 = blockIdx.x * BN;
    const int ty = tid >> 4;   // 0..15 -> 8 output rows each
    const int tx = tid & 15;   // 0..15 -> 8 output cols each

    unsigned long long acc[8][4];
#pragma unroll
    for (int i = 0; i < 8; i++)
#pragma unroll
        for (int j = 0; j < 4; j++) acc[i][j] = 0ull;

    for (int k0 = 0; k0 < K; k0 += BK) {
        // A tile: 128 rows x 16 cols = 512 float4, 2 per thread
#pragma unroll
        for (int it = 0; it < 2; it++) {
            int idx = it * 256 + tid;
            int ar = idx >> 2;
            int ac = (idx & 3) * 4;
            float4 av = *(const float4*)(A + (size_t)(row0 + ar) * K + k0 + ac);
            As[ac + 0][ar] = av.x;
            As[ac + 1][ar] = av.y;
            As[ac + 2][ar] = av.z;
            As[ac + 3][ar] = av.w;
        }
        // B tile: 16 rows x 128 cols = 512 float4, 2 per thread
#pragma unroll
        for (int it = 0; it < 2; it++) {
            int idx = it * 256 + tid;
            int br = idx >> 5;
            int bc = (idx & 31) * 4;
            *(float4*)&Bs[br][bc] =
                *(const float4*)(B + (size_t)(k0 + br) * N + col0 + bc);
        }
        __syncthreads();
#pragma unroll
        for (int k = 0; k < BK; k++) {
            float ar[8];
            *(float4*)&ar[0] = *(const float4*)&As[k][ty * 8];
            *(float4*)&ar[4] = *(const float4*)&As[k][ty * 8 + 4];
            ulonglong2 b01 = *(const ulonglong2*)&Bs[k][tx * 8];
            ulonglong2 b23 = *(const ulonglong2*)&Bs[k][tx * 8 + 4];
            unsigned long long bb0 = b01.x, bb1 = b01.y, bb2 = b23.x, bb3 = b23.y;
#pragma unroll
            for (int i = 0; i < 8; i++) {
                unsigned long long a2 = pack2(ar[i], ar[i]);
                fma2(acc[i][0], a2, bb0);
                fma2(acc[i][1], a2, bb1);
                fma2(acc[i][2], a2, bb2);
                fma2(acc[i][3], a2, bb3);
            }
        }
        __syncthreads();
    }

#pragma unroll
    for (int i = 0; i < 8; i++) {
        int r = row0 + ty * 8 + i;
        size_t off = (size_t)r * N + col0 + tx * 8;
        float o[8];
#pragma unroll
        for (int j2 = 0; j2 < 4; j2++) {
            float2 v = unpack2(acc[i][j2]);
            o[j2 * 2 + 0] = v.x;
            o[j2 * 2 + 1] = v.y;
        }
        if (EPI == 1) {
            const float* aux = Auxg + eoffC + off;
#pragma unroll
            for (int j = 0; j < 8; j++) {
                float xv = o[j];
                o[j] = (xv / (1.f + __expf(-xv))) * aux[j];   // silu(x)*aux
            }
        }
        *(float4*)(C + off) = *(float4*)&o[0];
        *(float4*)(C + off + 4) = *(float4*)&o[4];
    }
}

// ---------------- combine: out[s] = g1*eo[e1,c1] + g2*eo[e2,c2] -------------
__global__ void k_combine(float* __restrict__ out, int out_size) {
    int s = blockIdx.x;
    int sl1 = g_slot1[s], sl2 = g_slot2[s];
    float g1 = (sl1 >= 0) ? g_g1[s] : 0.f;
    float g2 = (sl2 >= 0) ? g_g2[s] : 0.f;
    float dn = fmaxf(g1 + g2, 1e-9f);
    g1 /= dn; g2 /= dn;
    const float4* r1 = (sl1 >= 0)
        ? (const float4*)(g_eo + ((size_t)g_idx1[s] * CAP + sl1) * DIM) : nullptr;
    const float4* r2 = (sl2 >= 0)
        ? (const float4*)(g_eo + ((size_t)g_idx2[s] * CAP + sl2) * DIM) : nullptr;
    float4* o = (float4*)(out + (size_t)s * DIM);
    for (int j = threadIdx.x; j < DIM / 4; j += blockDim.x) {
        float4 v = make_float4(0.f, 0.f, 0.f, 0.f);
        if (r1) { float4 t = r1[j]; v.x += g1 * t.x; v.y += g1 * t.y; v.z += g1 * t.z; v.w += g1 * t.w; }
        if (r2) { float4 t = r2[j]; v.x += g2 * t.x; v.y += g2 * t.y; v.z += g2 * t.z; v.w += g2 * t.w; }
        o[j] = v;
    }
    // auxiliary outputs (l_aux, exp_counts) if the output buffer carries them
    if (s == 0) {
        size_t base = (size_t)S_TOK * DIM;
        if ((size_t)out_size > base && threadIdx.x == 0) out[base] = g_laux;
        if ((size_t)out_size >= base + 1 + NE && threadIdx.x >= 1 && threadIdx.x <= NE)
            out[base + threadIdx.x] = (float)g_count1[threadIdx.x - 1];
    }
}

// ---------------- launch -----------------------------------------------------
extern "C" void kernel_launch(void* const* d_in, const int* in_sizes, int n_in,
                              void* d_out, int out_size) {
    (void)in_sizes; (void)n_in;
    const float* x  = (const float*)d_in[0];   // hidden_states [B,S_LEN,D]
    const float* wg = (const float*)d_in[1];   // [D,E]
    const float* w1 = (const float*)d_in[2];   // [E,D,F]
    const float* w3 = (const float*)d_in[3];   // [E,D,F]
    const float* w2 = (const float*)d_in[4];   // [E,F,D]
    float* out = (float*)d_out;

    void *p_xe, *p_t3, *p_h, *p_eo;
    cudaGetSymbolAddress(&p_xe, g_xe);
    cudaGetSymbolAddress(&p_t3, g_t3);
    cudaGetSymbolAddress(&p_h,  g_h);
    cudaGetSymbolAddress(&p_eo, g_eo);

    k_init<<<(NE * CAP + 255) / 256, 256>>>();
    k_logits<<<S_TOK, 128>>>(x, wg);
    k_top2<<<S_TOK / 256, 256>>>();
    k_scan<<<1, 256>>>();
    k_dispatch<<<NE * CAP, 256>>>(x);

    dim3 grid1(FF / BN, CAP / BM, NE);   // (43, 8, 8)
    sgemm<0><<<grid1, 256>>>((const float*)p_xe, w3, (float*)p_t3, nullptr,
                             CAP, FF, DIM);
    sgemm<1><<<grid1, 256>>>((const float*)p_xe, w1, (float*)p_h,
                             (const float*)p_t3, CAP, FF, DIM);
    dim3 grid2(DIM / BN, CAP / BM, NE);  // (16, 8, 8)
    sgemm<0><<<grid2, 256>>>((const float*)p_h, w2, (float*)p_eo, nullptr,
                             CAP, DIM, FF);

    k_combine<<<S_TOK, 256>>>(out, out_size);
}

// round 4
// speedup vs baseline: 2.4674x; 2.4674x over previous
#include <cuda_runtime.h>
#include <cuda_bf16.h>
#include <cstdint>

#define S_TOK 4096
#define DIM   2048
#define NE    8
#define FF    5504
#define CAP   1024

typedef __nv_bfloat16 bf16;

// ---------------- device-global scratch ------------------------------------
__device__ float g_logits[S_TOK * NE];
__device__ int   g_idx1[S_TOK], g_idx2[S_TOK];
__device__ float g_g1[S_TOK], g_g2[S_TOK];
__device__ int   g_slot1[S_TOK], g_slot2[S_TOK];
__device__ int   g_tok4slot[NE * CAP];
__device__ int   g_count1[NE];
__device__ float g_me[NE];
__device__ float g_laux;

__device__ bf16  g_ah[(size_t)NE * CAP * DIM];    // 32MB
__device__ bf16  g_al[(size_t)NE * CAP * DIM];
__device__ bf16  g_w1h[(size_t)NE * DIM * FF];    // 180MB each
__device__ bf16  g_w1l[(size_t)NE * DIM * FF];
__device__ bf16  g_w3h[(size_t)NE * DIM * FF];
__device__ bf16  g_w3l[(size_t)NE * DIM * FF];
__device__ bf16  g_w2h[(size_t)NE * FF * DIM];
__device__ bf16  g_w2l[(size_t)NE * FF * DIM];
__device__ float g_t1[(size_t)NE * CAP * FF];     // 180MB
__device__ float g_t3[(size_t)NE * CAP * FF];
__device__ bf16  g_hh[(size_t)NE * CAP * FF];     // 90MB
__device__ bf16  g_hl[(size_t)NE * CAP * FF];
__device__ float g_eo[(size_t)NE * CAP * DIM];    // 64MB

// ---------------- helpers ----------------------------------------------------
__device__ __forceinline__ uint32_t smem_to_u32(const void* p) {
    uint32_t a;
    asm("{ .reg .u64 t; cvta.to.shared.u64 t, %1; cvt.u32.u64 %0, t; }"
        : "=r"(a) : "l"(p));
    return a;
}
__device__ __forceinline__ void cpasync16(uint32_t dst, const void* src) {
    asm volatile("cp.async.cg.shared.global [%0], [%1], 16;" :: "r"(dst), "l"(src));
}
#define CP_COMMIT() asm volatile("cp.async.commit_group;" ::: "memory")
#define CP_WAIT1()  asm volatile("cp.async.wait_group 1;" ::: "memory")

__device__ __forceinline__ void ldsm_x4(uint32_t& r0, uint32_t& r1, uint32_t& r2,
                                        uint32_t& r3, uint32_t a) {
    asm volatile("ldmatrix.sync.aligned.m8n8.x4.shared.b16 {%0,%1,%2,%3}, [%4];"
                 : "=r"(r0), "=r"(r1), "=r"(r2), "=r"(r3) : "r"(a));
}
__device__ __forceinline__ void ldsm_x4t(uint32_t& r0, uint32_t& r1, uint32_t& r2,
                                         uint32_t& r3, uint32_t a) {
    asm volatile("ldmatrix.sync.aligned.m8n8.x4.trans.shared.b16 {%0,%1,%2,%3}, [%4];"
                 : "=r"(r0), "=r"(r1), "=r"(r2), "=r"(r3) : "r"(a));
}
__device__ __forceinline__ void mma16816(float* c, const uint32_t* a,
                                         uint32_t b0, uint32_t b1) {
    asm volatile("mma.sync.aligned.m16n8k16.row.col.f32.bf16.bf16.f32 "
                 "{%0,%1,%2,%3},{%4,%5,%6,%7},{%8,%9},{%0,%1,%2,%3};"
                 : "+f"(c[0]), "+f"(c[1]), "+f"(c[2]), "+f"(c[3])
                 : "r"(a[0]), "r"(a[1]), "r"(a[2]), "r"(a[3]), "r"(b0), "r"(b1));
}
__device__ __forceinline__ uint32_t pk(bf16 a, bf16 b) {
    return (uint32_t)__bfloat16_as_ushort(a) | ((uint32_t)__bfloat16_as_ushort(b) << 16);
}
__device__ __forceinline__ void split2(float v, bf16& h, bf16& l) {
    h = __float2bfloat16(v);
    l = __float2bfloat16(v - __bfloat162float(h));
}

// ---------------- gating (proven Round 1; k_scan smem-staged) ----------------
__global__ void k_init() {
    int i = blockIdx.x * blockDim.x + threadIdx.x;
    if (i < NE * CAP) g_tok4slot[i] = -1;
    if (i < NE) g_me[i] = 0.f;
}
__global__ void k_logits(const float* __restrict__ x, const float* __restrict__ wg) {
    int s = blockIdx.x;
    float acc[NE];
#pragma unroll
    for (int e = 0; e < NE; e++) acc[e] = 0.f;
    const float* xr = x + (size_t)s * DIM;
    for (int j = threadIdx.x; j < DIM; j += blockDim.x) {
        float xv = xr[j];
        float4 w0 = *(const float4*)(wg + (size_t)j * NE);
        float4 w1v = *(const float4*)(wg + (size_t)j * NE + 4);
        acc[0] += xv * w0.x;  acc[1] += xv * w0.y;
        acc[2] += xv * w0.z;  acc[3] += xv * w0.w;
        acc[4] += xv * w1v.x; acc[5] += xv * w1v.y;
        acc[6] += xv * w1v.z; acc[7] += xv * w1v.w;
    }
#pragma unroll
    for (int off = 16; off; off >>= 1)
#pragma unroll
        for (int e = 0; e < NE; e++)
            acc[e] += __shfl_down_sync(0xffffffffu, acc[e], off);
    __shared__ float red[4][NE];
    int lane = threadIdx.x & 31, wp = threadIdx.x >> 5;
    if (lane == 0)
#pragma unroll
        for (int e = 0; e < NE; e++) red[wp][e] = acc[e];
    __syncthreads();
    if (threadIdx.x < NE)
        g_logits[(size_t)s * NE + threadIdx.x] =
            red[0][threadIdx.x] + red[1][threadIdx.x] +
            red[2][threadIdx.x] + red[3][threadIdx.x];
}
__global__ void k_top2() {
    __shared__ float sme[NE];
    if (threadIdx.x < NE) sme[threadIdx.x] = 0.f;
    __syncthreads();
    int s = blockIdx.x * blockDim.x + threadIdx.x;
    float l[NE];
    float4 a = *(const float4*)(g_logits + (size_t)s * NE);
    float4 b = *(const float4*)(g_logits + (size_t)s * NE + 4);
    l[0]=a.x; l[1]=a.y; l[2]=a.z; l[3]=a.w; l[4]=b.x; l[5]=b.y; l[6]=b.z; l[7]=b.w;
    float mx = l[0];
#pragma unroll
    for (int e = 1; e < NE; e++) mx = fmaxf(mx, l[e]);
    float g[NE], sum = 0.f;
#pragma unroll
    for (int e = 0; e < NE; e++) { g[e] = __expf(l[e] - mx); sum += g[e]; }
    float inv = 1.f / sum;
    int i1 = 0; float b1 = l[0];
#pragma unroll
    for (int e = 1; e < NE; e++) if (l[e] > b1) { b1 = l[e]; i1 = e; }
    int i2 = 0; float b2 = -3.0e38f;
#pragma unroll
    for (int e = 0; e < NE; e++) if (e != i1 && l[e] > b2) { b2 = l[e]; i2 = e; }
    g_idx1[s] = i1; g_idx2[s] = i2;
    g_g1[s] = g[i1] * inv; g_g2[s] = g[i2] * inv;
#pragma unroll
    for (int e = 0; e < NE; e++) atomicAdd(&sme[e], g[e] * inv);
    __syncthreads();
    if (threadIdx.x < NE) atomicAdd(&g_me[threadIdx.x], sme[threadIdx.x]);
}
__global__ void k_scan() {
    __shared__ int si1[S_TOK], si2[S_TOK];
    int tid = threadIdx.x;
    for (int i = tid; i < S_TOK; i += blockDim.x) { si1[i] = g_idx1[i]; si2[i] = g_idx2[i]; }
    __syncthreads();
    int lane = tid & 31, e = tid >> 5;
    unsigned lm = (1u << lane) - 1u;
    if (e < NE) {
        int c1 = 0;
        for (int s0 = 0; s0 < S_TOK; s0 += 32) {
            int s = s0 + lane;
            int m = (si1[s] == e);
            unsigned bal = __ballot_sync(0xffffffffu, m);
            if (m) {
                int pos = c1 + __popc(bal & lm);
                if (pos < CAP) { g_slot1[s] = pos; g_tok4slot[e * CAP + pos] = s; }
                else g_slot1[s] = -1;
            }
            c1 += __popc(bal);
        }
        if (lane == 0) g_count1[e] = c1;
        int c2 = c1;
        for (int s0 = 0; s0 < S_TOK; s0 += 32) {
            int s = s0 + lane;
            int m = (si2[s] == e);
            unsigned bal = __ballot_sync(0xffffffffu, m);
            if (m) {
                int pos = c2 + __popc(bal & lm);
                if (pos < CAP) { g_slot2[s] = pos; g_tok4slot[e * CAP + pos] = s; }
                else g_slot2[s] = -1;
            }
            c2 += __popc(bal);
        }
    }
    __syncthreads();
    if (tid == 0) {
        float acc = 0.f;
        for (int i = 0; i < NE; i++)
            acc += (g_me[i] / (float)S_TOK) * ((float)g_count1[i] / (float)S_TOK);
        g_laux = acc * (float)NE;
    }
}

// ---------------- dispatch: gather token rows -> Ah/Al bf16 -----------------
__global__ void k_dispatch_split(const float* __restrict__ x) {
    int slot = blockIdx.x;
    int s = g_tok4slot[slot];
    uint2* ah = (uint2*)(g_ah + (size_t)slot * DIM);
    uint2* al = (uint2*)(g_al + (size_t)slot * DIM);
    if (s >= 0) {
        const float4* xr = (const float4*)(x + (size_t)s * DIM);
        for (int j = threadIdx.x; j < DIM / 4; j += blockDim.x) {
            float4 v = xr[j];
            bf16 h0, l0, h1, l1, h2, l2, h3, l3;
            split2(v.x, h0, l0); split2(v.y, h1, l1);
            split2(v.z, h2, l2); split2(v.w, h3, l3);
            ah[j] = make_uint2(pk(h0, h1), pk(h2, h3));
            al[j] = make_uint2(pk(l0, l1), pk(l2, l3));
        }
    } else {
        uint2 z = make_uint2(0u, 0u);
        for (int j = threadIdx.x; j < DIM / 4; j += blockDim.x) { ah[j] = z; al[j] = z; }
    }
}

// ---------------- weight split: fp32 -> hi/lo bf16 --------------------------
__global__ void k_wsplit(const float4* __restrict__ src, uint2* __restrict__ hh,
                         uint2* __restrict__ ll, size_t n4) {
    size_t i = (size_t)blockIdx.x * blockDim.x + threadIdx.x;
    if (i >= n4) return;
    float4 v = src[i];
    bf16 h0, l0, h1, l1, h2, l2, h3, l3;
    split2(v.x, h0, l0); split2(v.y, h1, l1);
    split2(v.z, h2, l2); split2(v.w, h3, l3);
    hh[i] = make_uint2(pk(h0, h1), pk(h2, h3));
    ll[i] = make_uint2(pk(l0, l1), pk(l2, l3));
}

// ---------------- swiglu + split: h = silu(t1)*t3 -> hh/hl ------------------
__global__ void k_swiglu(const float4* __restrict__ t1, const float4* __restrict__ t3,
                         uint2* __restrict__ hh, uint2* __restrict__ hl, size_t n4) {
    size_t i = (size_t)blockIdx.x * blockDim.x + threadIdx.x;
    if (i >= n4) return;
    float4 a = t1[i], b = t3[i];
    float h0 = a.x / (1.f + __expf(-a.x)) * b.x;
    float h1 = a.y / (1.f + __expf(-a.y)) * b.y;
    float h2 = a.z / (1.f + __expf(-a.z)) * b.z;
    float h3 = a.w / (1.f + __expf(-a.w)) * b.w;
    bf16 x0, y0, x1, y1, x2, y2, x3, y3;
    split2(h0, x0, y0); split2(h1, x1, y1);
    split2(h2, x2, y2); split2(h3, x3, y3);
    hh[i] = make_uint2(pk(x0, x1), pk(x2, x3));
    hl[i] = make_uint2(pk(y0, y1), pk(y2, y3));
}

// ---------------- split-bf16 grouped GEMM via mma.sync (HMMA) ---------------
// C[e][M=CAP][N] = Ah@Bh + Al@Bh + Ah@Bl  (fp32 out)
// BM=128 BN=128 BK=32, 8 warps (2 M x 4 N), warp tile 64x32, 3-stage cp.async.
#define ASTRIDE 80u     // 32 bf16 = 64B + 16B pad (conflict-free ldmatrix)
#define BSTRIDE 272u    // 128 bf16 = 256B + 16B pad
#define STG     (128u * ASTRIDE + 32u * BSTRIDE)   // 10240 + 8704 = 18944
#define GSMEM   (3u * STG)                          // 56832

__global__ void __launch_bounds__(256, 2)
k_gemm_mma(const bf16* __restrict__ Ah, const bf16* __restrict__ Al,
           const bf16* __restrict__ Bh, const bf16* __restrict__ Bl,
           float* __restrict__ Cg, int N, int K) {
    extern __shared__ __align__(16) uint8_t smem[];
    const int M = CAP;
    int tid = threadIdx.x, lane = tid & 31, wid = tid >> 5;
    int wm = wid & 1, wn = wid >> 1;
    int n0 = blockIdx.x * 128, m0 = blockIdx.y * 128, e = blockIdx.z;
    const bf16* A0 = Ah + (size_t)e * M * K;
    const bf16* A1 = Al + (size_t)e * M * K;
    const bf16* B0 = Bh + (size_t)e * K * N;
    const bf16* B1 = Bl + (size_t)e * K * N;
    float* C = Cg + (size_t)e * M * N;
    const int KCH = K / 32, NIT = 3 * KCH;
    uint32_t sb = smem_to_u32(smem);

    float acc[4][4][4];
#pragma unroll
    for (int a = 0; a < 4; a++)
#pragma unroll
        for (int b = 0; b < 4; b++)
#pragma unroll
            for (int c = 0; c < 4; c++) acc[a][b][c] = 0.f;

    auto load_stage = [&](int i, int slot) {
        int t = (i >= 2 * KCH) ? 2 : ((i >= KCH) ? 1 : 0);
        int kc = i - t * KCH;
        const bf16* A = (t == 1) ? A1 : A0;
        const bf16* B = (t == 2) ? B1 : B0;
        uint32_t as = sb + (uint32_t)slot * STG;
        uint32_t bs = as + 128u * ASTRIDE;
#pragma unroll
        for (int j = 0; j < 2; j++) {
            int id = tid + j * 256;
            int row = id >> 2, c = id & 3;
            cpasync16(as + (uint32_t)row * ASTRIDE + c * 16,
                      A + (size_t)(m0 + row) * K + kc * 32 + c * 8);
        }
#pragma unroll
        for (int j = 0; j < 2; j++) {
            int id = tid + j * 256;
            int k = id >> 4, c = id & 15;
            cpasync16(bs + (uint32_t)k * BSTRIDE + c * 16,
                      B + (size_t)(kc * 32 + k) * N + n0 + c * 8);
        }
    };

    load_stage(0, 0); CP_COMMIT();
    load_stage(1, 1); CP_COMMIT();

    int mm = lane >> 3;
    int rowin = (mm & 1) * 8 + (lane & 7);
    int c0 = mm >> 1;
    uint32_t aOff = (uint32_t)(wm * 64 + rowin) * ASTRIDE + (uint32_t)c0 * 16;
    int p = lane >> 4, mrow = (lane >> 3) & 1;
    int kin = mrow * 8 + (lane & 7);
    uint32_t bOff = 128u * ASTRIDE + (uint32_t)kin * BSTRIDE + (uint32_t)(wn * 4 + p) * 16;

    int slot = 0;
    for (int i = 0; i < NIT; i++) {
        CP_WAIT1();
        __syncthreads();
        uint32_t st = sb + (uint32_t)slot * STG;
#pragma unroll
        for (int s = 0; s < 2; s++) {
            uint32_t a[4][4], b[2][4];
#pragma unroll
            for (int mt = 0; mt < 4; mt++)
                ldsm_x4(a[mt][0], a[mt][1], a[mt][2], a[mt][3],
                        st + aOff + (uint32_t)mt * (16u * ASTRIDE) + (uint32_t)s * 32);
            ldsm_x4t(b[0][0], b[0][1], b[0][2], b[0][3],
                     st + bOff + (uint32_t)s * (16u * BSTRIDE));
            ldsm_x4t(b[1][0], b[1][1], b[1][2], b[1][3],
                     st + bOff + (uint32_t)s * (16u * BSTRIDE) + 32u);
#pragma unroll
            for (int mt = 0; mt < 4; mt++)
#pragma unroll
                for (int nt = 0; nt < 4; nt++)
                    mma16816(acc[mt][nt], a[mt], b[nt >> 1][(nt & 1) * 2],
                             b[nt >> 1][(nt & 1) * 2 + 1]);
        }
        if (i + 2 < NIT) load_stage(i + 2, slot == 0 ? 2 : slot - 1);
        CP_COMMIT();
        slot = (slot == 2) ? 0 : slot + 1;
    }

    int rg = lane >> 2, cgi = (lane & 3) * 2;
#pragma unroll
    for (int mt = 0; mt < 4; mt++)
#pragma unroll
        for (int nt = 0; nt < 4; nt++) {
            int row = m0 + wm * 64 + mt * 16 + rg;
            int col = n0 + wn * 32 + nt * 8 + cgi;
            *(float2*)(C + (size_t)row * N + col) =
                make_float2(acc[mt][nt][0], acc[mt][nt][1]);
            *(float2*)(C + (size_t)(row + 8) * N + col) =
                make_float2(acc[mt][nt][2], acc[mt][nt][3]);
        }
}

// ---------------- combine ----------------------------------------------------
__global__ void k_combine(float* __restrict__ out, int out_size) {
    int s = blockIdx.x;
    int sl1 = g_slot1[s], sl2 = g_slot2[s];
    float g1 = (sl1 >= 0) ? g_g1[s] : 0.f;
    float g2 = (sl2 >= 0) ? g_g2[s] : 0.f;
    float dn = fmaxf(g1 + g2, 1e-9f);
    g1 /= dn; g2 /= dn;
    const float4* r1 = (sl1 >= 0)
        ? (const float4*)(g_eo + ((size_t)g_idx1[s] * CAP + sl1) * DIM) : nullptr;
    const float4* r2 = (sl2 >= 0)
        ? (const float4*)(g_eo + ((size_t)g_idx2[s] * CAP + sl2) * DIM) : nullptr;
    float4* o = (float4*)(out + (size_t)s * DIM);
    for (int j = threadIdx.x; j < DIM / 4; j += blockDim.x) {
        float4 v = make_float4(0.f, 0.f, 0.f, 0.f);
        if (r1) { float4 t = r1[j]; v.x += g1 * t.x; v.y += g1 * t.y; v.z += g1 * t.z; v.w += g1 * t.w; }
        if (r2) { float4 t = r2[j]; v.x += g2 * t.x; v.y += g2 * t.y; v.z += g2 * t.z; v.w += g2 * t.w; }
        o[j] = v;
    }
    if (s == 0) {
        size_t base = (size_t)S_TOK * DIM;
        if ((size_t)out_size > base && threadIdx.x == 0) out[base] = g_laux;
        if ((size_t)out_size >= base + 1 + NE && threadIdx.x >= 1 && threadIdx.x <= NE)
            out[base + threadIdx.x] = (float)g_count1[threadIdx.x - 1];
    }
}

// ---------------- launch -----------------------------------------------------
extern "C" void kernel_launch(void* const* d_in, const int* in_sizes, int n_in,
                              void* d_out, int out_size) {
    (void)in_sizes; (void)n_in;
    const float* x  = (const float*)d_in[0];
    const float* wg = (const float*)d_in[1];
    const float* w1 = (const float*)d_in[2];
    const float* w3 = (const float*)d_in[3];
    const float* w2 = (const float*)d_in[4];
    float* out = (float*)d_out;

    cudaFuncSetAttribute(k_gemm_mma, cudaFuncAttributeMaxDynamicSharedMemorySize, GSMEM);

    void *p_ah, *p_al, *p_w1h, *p_w1l, *p_w3h, *p_w3l, *p_w2h, *p_w2l;
    void *p_t1, *p_t3, *p_hh, *p_hl, *p_eo;
    cudaGetSymbolAddress(&p_ah, g_ah);   cudaGetSymbolAddress(&p_al, g_al);
    cudaGetSymbolAddress(&p_w1h, g_w1h); cudaGetSymbolAddress(&p_w1l, g_w1l);
    cudaGetSymbolAddress(&p_w3h, g_w3h); cudaGetSymbolAddress(&p_w3l, g_w3l);
    cudaGetSymbolAddress(&p_w2h, g_w2h); cudaGetSymbolAddress(&p_w2l, g_w2l);
    cudaGetSymbolAddress(&p_t1, g_t1);   cudaGetSymbolAddress(&p_t3, g_t3);
    cudaGetSymbolAddress(&p_hh, g_hh);   cudaGetSymbolAddress(&p_hl, g_hl);
    cudaGetSymbolAddress(&p_eo, g_eo);

    k_init<<<(NE * CAP + 255) / 256, 256>>>();
    k_logits<<<S_TOK, 128>>>(x, wg);
    k_top2<<<S_TOK / 256, 256>>>();
    k_scan<<<1, 256>>>();
    k_dispatch_split<<<NE * CAP, 256>>>(x);

    const size_t NW4 = (size_t)NE * DIM * FF / 4;   // 22,544,384
    int wgrid = (int)((NW4 + 255) / 256);
    k_wsplit<<<wgrid, 256>>>((const float4*)w1, (uint2*)p_w1h, (uint2*)p_w1l, NW4);
    k_wsplit<<<wgrid, 256>>>((const float4*)w3, (uint2*)p_w3h, (uint2*)p_w3l, NW4);
    k_wsplit<<<wgrid, 256>>>((const float4*)w2, (uint2*)p_w2h, (uint2*)p_w2l, NW4);

    dim3 grid1(FF / 128, CAP / 128, NE);   // (43, 8, 8)
    k_gemm_mma<<<grid1, 256, GSMEM>>>((const bf16*)p_ah, (const bf16*)p_al,
                                      (const bf16*)p_w1h, (const bf16*)p_w1l,
                                      (float*)p_t1, FF, DIM);
    k_gemm_mma<<<grid1, 256, GSMEM>>>((const bf16*)p_ah, (const bf16*)p_al,
                                      (const bf16*)p_w3h, (const bf16*)p_w3l,
                                      (float*)p_t3, FF, DIM);

    const size_t NH4 = (size_t)NE * CAP * FF / 4;   // 11,272,192
    k_swiglu<<<(int)((NH4 + 255) / 256), 256>>>(
        (const float4*)p_t1, (const float4*)p_t3, (uint2*)p_hh, (uint2*)p_hl, NH4);

    dim3 grid2(DIM / 128, CAP / 128, NE);  // (16, 8, 8)
    k_gemm_mma<<<grid2, 256, GSMEM>>>((const bf16*)p_hh, (const bf16*)p_hl,
                                      (const bf16*)p_w2h, (const bf16*)p_w2l,
                                      (float*)p_eo, DIM, FF);

    k_combine<<<S_TOK, 256>>>(out, out_size);
}

// round 5
// speedup vs baseline: 2.6564x; 1.0766x over previous
#include <cuda_runtime.h>
#include <cuda_bf16.h>
#include <cstdint>

#define S_TOK 4096
#define DIM   2048
#define NE    8
#define FF    5504
#define CAP   1024

typedef __nv_bfloat16 bf16;

// ---------------- device-global scratch ------------------------------------
__device__ float g_logits[S_TOK * NE];
__device__ int   g_idx1[S_TOK], g_idx2[S_TOK];
__device__ float g_g1[S_TOK], g_g2[S_TOK];
__device__ int   g_slot1[S_TOK], g_slot2[S_TOK];
__device__ int   g_tok4slot[NE * CAP];
__device__ int   g_count1[NE];
__device__ float g_me[NE];
__device__ float g_laux;

__device__ bf16  g_ah[(size_t)NE * CAP * DIM];
__device__ bf16  g_al[(size_t)NE * CAP * DIM];
__device__ bf16  g_w1h[(size_t)NE * DIM * FF];
__device__ bf16  g_w1l[(size_t)NE * DIM * FF];
__device__ bf16  g_w3h[(size_t)NE * DIM * FF];
__device__ bf16  g_w3l[(size_t)NE * DIM * FF];
__device__ bf16  g_w2h[(size_t)NE * FF * DIM];
__device__ bf16  g_w2l[(size_t)NE * FF * DIM];
__device__ float g_t1[(size_t)NE * CAP * FF];
__device__ bf16  g_hh[(size_t)NE * CAP * FF];
__device__ bf16  g_hl[(size_t)NE * CAP * FF];
__device__ float g_eo[(size_t)NE * CAP * DIM];

// ---------------- helpers ----------------------------------------------------
__device__ __forceinline__ uint32_t smem_to_u32(const void* p) {
    uint32_t a;
    asm("{ .reg .u64 t; cvta.to.shared.u64 t, %1; cvt.u32.u64 %0, t; }"
        : "=r"(a) : "l"(p));
    return a;
}
__device__ __forceinline__ void cpasync16(uint32_t dst, const void* src) {
    asm volatile("cp.async.cg.shared.global [%0], [%1], 16;" :: "r"(dst), "l"(src));
}
#define CP_COMMIT() asm volatile("cp.async.commit_group;" ::: "memory")
#define CP_WAIT1()  asm volatile("cp.async.wait_group 1;" ::: "memory")
#define CP_WAIT0()  asm volatile("cp.async.wait_group 0;" ::: "memory")

__device__ __forceinline__ void ldsm_x4(uint32_t& r0, uint32_t& r1, uint32_t& r2,
                                        uint32_t& r3, uint32_t a) {
    asm volatile("ldmatrix.sync.aligned.m8n8.x4.shared.b16 {%0,%1,%2,%3}, [%4];"
                 : "=r"(r0), "=r"(r1), "=r"(r2), "=r"(r3) : "r"(a));
}
__device__ __forceinline__ void ldsm_x4t(uint32_t& r0, uint32_t& r1, uint32_t& r2,
                                         uint32_t& r3, uint32_t a) {
    asm volatile("ldmatrix.sync.aligned.m8n8.x4.trans.shared.b16 {%0,%1,%2,%3}, [%4];"
                 : "=r"(r0), "=r"(r1), "=r"(r2), "=r"(r3) : "r"(a));
}
__device__ __forceinline__ void mma16816(float* c, const uint32_t* a,
                                         uint32_t b0, uint32_t b1) {
    asm volatile("mma.sync.aligned.m16n8k16.row.col.f32.bf16.bf16.f32 "
                 "{%0,%1,%2,%3},{%4,%5,%6,%7},{%8,%9},{%0,%1,%2,%3};"
                 : "+f"(c[0]), "+f"(c[1]), "+f"(c[2]), "+f"(c[3])
                 : "r"(a[0]), "r"(a[1]), "r"(a[2]), "r"(a[3]), "r"(b0), "r"(b1));
}
__device__ __forceinline__ uint32_t pk(bf16 a, bf16 b) {
    return (uint32_t)__bfloat16_as_ushort(a) | ((uint32_t)__bfloat16_as_ushort(b) << 16);
}
__device__ __forceinline__ void split2(float v, bf16& h, bf16& l) {
    h = __float2bfloat16(v);
    l = __float2bfloat16(v - __bfloat162float(h));
}

// ---------------- gating ------------------------------------------------------
__global__ void k_init() {
    int i = blockIdx.x * blockDim.x + threadIdx.x;
    if (i < NE * CAP) g_tok4slot[i] = -1;
    if (i < NE) g_me[i] = 0.f;
}
__global__ void k_logits(const float* __restrict__ x, const float* __restrict__ wg) {
    int s = blockIdx.x;
    float acc[NE];
#pragma unroll
    for (int e = 0; e < NE; e++) acc[e] = 0.f;
    const float* xr = x + (size_t)s * DIM;
    for (int j = threadIdx.x; j < DIM; j += blockDim.x) {
        float xv = xr[j];
        float4 w0 = *(const float4*)(wg + (size_t)j * NE);
        float4 w1v = *(const float4*)(wg + (size_t)j * NE + 4);
        acc[0] += xv * w0.x;  acc[1] += xv * w0.y;
        acc[2] += xv * w0.z;  acc[3] += xv * w0.w;
        acc[4] += xv * w1v.x; acc[5] += xv * w1v.y;
        acc[6] += xv * w1v.z; acc[7] += xv * w1v.w;
    }
#pragma unroll
    for (int off = 16; off; off >>= 1)
#pragma unroll
        for (int e = 0; e < NE; e++)
            acc[e] += __shfl_down_sync(0xffffffffu, acc[e], off);
    __shared__ float red[4][NE];
    int lane = threadIdx.x & 31, wp = threadIdx.x >> 5;
    if (lane == 0)
#pragma unroll
        for (int e = 0; e < NE; e++) red[wp][e] = acc[e];
    __syncthreads();
    if (threadIdx.x < NE)
        g_logits[(size_t)s * NE + threadIdx.x] =
            red[0][threadIdx.x] + red[1][threadIdx.x] +
            red[2][threadIdx.x] + red[3][threadIdx.x];
}
__global__ void k_top2() {
    __shared__ float sme[NE];
    if (threadIdx.x < NE) sme[threadIdx.x] = 0.f;
    __syncthreads();
    int s = blockIdx.x * blockDim.x + threadIdx.x;
    float l[NE];
    float4 a = *(const float4*)(g_logits + (size_t)s * NE);
    float4 b = *(const float4*)(g_logits + (size_t)s * NE + 4);
    l[0]=a.x; l[1]=a.y; l[2]=a.z; l[3]=a.w; l[4]=b.x; l[5]=b.y; l[6]=b.z; l[7]=b.w;
    float mx = l[0];
#pragma unroll
    for (int e = 1; e < NE; e++) mx = fmaxf(mx, l[e]);
    float g[NE], sum = 0.f;
#pragma unroll
    for (int e = 0; e < NE; e++) { g[e] = __expf(l[e] - mx); sum += g[e]; }
    float inv = 1.f / sum;
    int i1 = 0; float b1 = l[0];
#pragma unroll
    for (int e = 1; e < NE; e++) if (l[e] > b1) { b1 = l[e]; i1 = e; }
    int i2 = 0; float b2 = -3.0e38f;
#pragma unroll
    for (int e = 0; e < NE; e++) if (e != i1 && l[e] > b2) { b2 = l[e]; i2 = e; }
    g_idx1[s] = i1; g_idx2[s] = i2;
    g_g1[s] = g[i1] * inv; g_g2[s] = g[i2] * inv;
#pragma unroll
    for (int e = 0; e < NE; e++) atomicAdd(&sme[e], g[e] * inv);
    __syncthreads();
    if (threadIdx.x < NE) atomicAdd(&g_me[threadIdx.x], sme[threadIdx.x]);
}
__global__ void k_scan() {
    __shared__ int si1[S_TOK], si2[S_TOK];
    int tid = threadIdx.x;
    for (int i = tid; i < S_TOK; i += blockDim.x) { si1[i] = g_idx1[i]; si2[i] = g_idx2[i]; }
    __syncthreads();
    int lane = tid & 31, e = tid >> 5;
    unsigned lm = (1u << lane) - 1u;
    if (e < NE) {
        int c1 = 0;
        for (int s0 = 0; s0 < S_TOK; s0 += 32) {
            int s = s0 + lane;
            int m = (si1[s] == e);
            unsigned bal = __ballot_sync(0xffffffffu, m);
            if (m) {
                int pos = c1 + __popc(bal & lm);
                if (pos < CAP) { g_slot1[s] = pos; g_tok4slot[e * CAP + pos] = s; }
                else g_slot1[s] = -1;
            }
            c1 += __popc(bal);
        }
        if (lane == 0) g_count1[e] = c1;
        int c2 = c1;
        for (int s0 = 0; s0 < S_TOK; s0 += 32) {
            int s = s0 + lane;
            int m = (si2[s] == e);
            unsigned bal = __ballot_sync(0xffffffffu, m);
            if (m) {
                int pos = c2 + __popc(bal & lm);
                if (pos < CAP) { g_slot2[s] = pos; g_tok4slot[e * CAP + pos] = s; }
                else g_slot2[s] = -1;
            }
            c2 += __popc(bal);
        }
    }
    __syncthreads();
    if (tid == 0) {
        float acc = 0.f;
        for (int i = 0; i < NE; i++)
            acc += (g_me[i] / (float)S_TOK) * ((float)g_count1[i] / (float)S_TOK);
        g_laux = acc * (float)NE;
    }
}

// ---------------- dispatch: gather token rows -> Ah/Al bf16 -----------------
__global__ void k_dispatch_split(const float* __restrict__ x) {
    int slot = blockIdx.x;
    int s = g_tok4slot[slot];
    uint2* ah = (uint2*)(g_ah + (size_t)slot * DIM);
    uint2* al = (uint2*)(g_al + (size_t)slot * DIM);
    if (s >= 0) {
        const float4* xr = (const float4*)(x + (size_t)s * DIM);
        for (int j = threadIdx.x; j < DIM / 4; j += blockDim.x) {
            float4 v = xr[j];
            bf16 h0, l0, h1, l1, h2, l2, h3, l3;
            split2(v.x, h0, l0); split2(v.y, h1, l1);
            split2(v.z, h2, l2); split2(v.w, h3, l3);
            ah[j] = make_uint2(pk(h0, h1), pk(h2, h3));
            al[j] = make_uint2(pk(l0, l1), pk(l2, l3));
        }
    } else {
        uint2 z = make_uint2(0u, 0u);
        for (int j = threadIdx.x; j < DIM / 4; j += blockDim.x) { ah[j] = z; al[j] = z; }
    }
}

// ---------------- weight split ----------------------------------------------
__global__ void k_wsplit(const float4* __restrict__ src, uint2* __restrict__ hh,
                         uint2* __restrict__ ll, size_t n4) {
    size_t i = (size_t)blockIdx.x * blockDim.x + threadIdx.x;
    if (i >= n4) return;
    float4 v = src[i];
    bf16 h0, l0, h1, l1, h2, l2, h3, l3;
    split2(v.x, h0, l0); split2(v.y, h1, l1);
    split2(v.z, h2, l2); split2(v.w, h3, l3);
    hh[i] = make_uint2(pk(h0, h1), pk(h2, h3));
    ll[i] = make_uint2(pk(l0, l1), pk(l2, l3));
}

// ---------------- fused split-bf16 HMMA GEMM --------------------------------
// C = Ah@Bh + Ah@Bl + Al@Bh, single K-pass, all operands in one smem stage.
// EPI 0: write fp32 C.  EPI 1: read Aux(t1), h=silu(aux)*acc -> hh/hl bf16.
#define ASTRIDE 80u
#define BSTRIDE 272u
#define A_SZ    (128u * ASTRIDE)          // 10240
#define B_SZ    (32u * BSTRIDE)           // 8704
#define OFF_AH  0u
#define OFF_AL  A_SZ
#define OFF_BH  (2u * A_SZ)
#define OFF_BL  (2u * A_SZ + B_SZ)
#define STG     (2u * A_SZ + 2u * B_SZ)   // 37888
#define GSMEM   (2u * STG)                // 75776

template <int EPI>
__global__ void __launch_bounds__(256, 2)
k_gemm_f(const bf16* __restrict__ Ahg, const bf16* __restrict__ Alg,
         const bf16* __restrict__ Bhg, const bf16* __restrict__ Blg,
         float* __restrict__ Cg, const float* __restrict__ Auxg,
         bf16* __restrict__ Hh, bf16* __restrict__ Hl, int N, int K) {
    extern __shared__ __align__(16) uint8_t smem[];
    const int M = CAP;
    int tid = threadIdx.x, lane = tid & 31, wid = tid >> 5;
    int wm = wid & 1, wn = wid >> 1;
    int n0 = blockIdx.x * 128, m0 = blockIdx.y * 128, e = blockIdx.z;
    const bf16* A0 = Ahg + (size_t)e * M * K;
    const bf16* A1 = Alg + (size_t)e * M * K;
    const bf16* B0 = Bhg + (size_t)e * K * N;
    const bf16* B1 = Blg + (size_t)e * K * N;
    const int NIT = K / 32;
    uint32_t sb = smem_to_u32(smem);

    float acc[4][4][4];
#pragma unroll
    for (int a = 0; a < 4; a++)
#pragma unroll
        for (int b = 0; b < 4; b++)
#pragma unroll
            for (int c = 0; c < 4; c++) acc[a][b][c] = 0.f;

    auto load_stage = [&](int kc, int slot) {
        uint32_t st = sb + (uint32_t)slot * STG;
#pragma unroll
        for (int j = 0; j < 2; j++) {
            int id = tid + j * 256;
            int row = id >> 2, c = id & 3;
            const size_t ga = (size_t)(m0 + row) * K + kc * 32 + c * 8;
            cpasync16(st + OFF_AH + (uint32_t)row * ASTRIDE + c * 16, A0 + ga);
            cpasync16(st + OFF_AL + (uint32_t)row * ASTRIDE + c * 16, A1 + ga);
        }
#pragma unroll
        for (int j = 0; j < 2; j++) {
            int id = tid + j * 256;
            int k = id >> 4, c = id & 15;
            const size_t gb = (size_t)(kc * 32 + k) * N + n0 + c * 8;
            cpasync16(st + OFF_BH + (uint32_t)k * BSTRIDE + c * 16, B0 + gb);
            cpasync16(st + OFF_BL + (uint32_t)k * BSTRIDE + c * 16, B1 + gb);
        }
    };

    // per-lane ldmatrix offsets (Round-4 proven layout)
    int mm = lane >> 3;
    int rowin = (mm & 1) * 8 + (lane & 7);
    int c0 = mm >> 1;
    uint32_t aOff = (uint32_t)(wm * 64 + rowin) * ASTRIDE + (uint32_t)c0 * 16;
    int p = lane >> 4, mrow = (lane >> 3) & 1;
    int kin = mrow * 8 + (lane & 7);
    uint32_t bOff = (uint32_t)kin * BSTRIDE + (uint32_t)(wn * 4 + p) * 16;

    load_stage(0, 0); CP_COMMIT();
    for (int i = 0; i < NIT; i++) {
        int cur = i & 1;
        if (i + 1 < NIT) { load_stage(i + 1, cur ^ 1); CP_COMMIT(); CP_WAIT1(); }
        else             { CP_WAIT0(); }
        __syncthreads();
        uint32_t st = sb + (uint32_t)cur * STG;
#pragma unroll
        for (int s = 0; s < 2; s++) {
            uint32_t a[4][4], bh[2][4], bl[2][4];
#pragma unroll
            for (int mt = 0; mt < 4; mt++)
                ldsm_x4(a[mt][0], a[mt][1], a[mt][2], a[mt][3],
                        st + OFF_AH + aOff + (uint32_t)mt * (16u * ASTRIDE) + (uint32_t)s * 32);
            ldsm_x4t(bh[0][0], bh[0][1], bh[0][2], bh[0][3],
                     st + OFF_BH + bOff + (uint32_t)s * (16u * BSTRIDE));
            ldsm_x4t(bh[1][0], bh[1][1], bh[1][2], bh[1][3],
                     st + OFF_BH + bOff + (uint32_t)s * (16u * BSTRIDE) + 32u);
            ldsm_x4t(bl[0][0], bl[0][1], bl[0][2], bl[0][3],
                     st + OFF_BL + bOff + (uint32_t)s * (16u * BSTRIDE));
            ldsm_x4t(bl[1][0], bl[1][1], bl[1][2], bl[1][3],
                     st + OFF_BL + bOff + (uint32_t)s * (16u * BSTRIDE) + 32u);
#pragma unroll
            for (int mt = 0; mt < 4; mt++)
#pragma unroll
                for (int nt = 0; nt < 4; nt++)
                    mma16816(acc[mt][nt], a[mt], bh[nt >> 1][(nt & 1) * 2],
                             bh[nt >> 1][(nt & 1) * 2 + 1]);
#pragma unroll
            for (int mt = 0; mt < 4; mt++)
#pragma unroll
                for (int nt = 0; nt < 4; nt++)
                    mma16816(acc[mt][nt], a[mt], bl[nt >> 1][(nt & 1) * 2],
                             bl[nt >> 1][(nt & 1) * 2 + 1]);
#pragma unroll
            for (int mt = 0; mt < 4; mt++)
                ldsm_x4(a[mt][0], a[mt][1], a[mt][2], a[mt][3],
                        st + OFF_AL + aOff + (uint32_t)mt * (16u * ASTRIDE) + (uint32_t)s * 32);
#pragma unroll
            for (int mt = 0; mt < 4; mt++)
#pragma unroll
                for (int nt = 0; nt < 4; nt++)
                    mma16816(acc[mt][nt], a[mt], bh[nt >> 1][(nt & 1) * 2],
                             bh[nt >> 1][(nt & 1) * 2 + 1]);
        }
        __syncthreads();
    }

    int rg = lane >> 2, cgi = (lane & 3) * 2;
    size_t ebase = (size_t)e * M * N;
#pragma unroll
    for (int mt = 0; mt < 4; mt++)
#pragma unroll
        for (int nt = 0; nt < 4; nt++) {
            int row = m0 + wm * 64 + mt * 16 + rg;
            int col = n0 + wn * 32 + nt * 8 + cgi;
            size_t o0 = ebase + (size_t)row * N + col;
            size_t o1 = ebase + (size_t)(row + 8) * N + col;
            if (EPI == 0) {
                *(float2*)(Cg + o0) = make_float2(acc[mt][nt][0], acc[mt][nt][1]);
                *(float2*)(Cg + o1) = make_float2(acc[mt][nt][2], acc[mt][nt][3]);
            } else {
                float2 t0 = *(const float2*)(Auxg + o0);
                float2 t1 = *(const float2*)(Auxg + o1);
                float h0 = t0.x / (1.f + __expf(-t0.x)) * acc[mt][nt][0];
                float h1 = t0.y / (1.f + __expf(-t0.y)) * acc[mt][nt][1];
                float h2 = t1.x / (1.f + __expf(-t1.x)) * acc[mt][nt][2];
                float h3 = t1.y / (1.f + __expf(-t1.y)) * acc[mt][nt][3];
                bf16 x0, y0, x1, y1, x2, y2, x3, y3;
                split2(h0, x0, y0); split2(h1, x1, y1);
                split2(h2, x2, y2); split2(h3, x3, y3);
                *(uint32_t*)(Hh + o0) = pk(x0, x1);
                *(uint32_t*)(Hl + o0) = pk(y0, y1);
                *(uint32_t*)(Hh + o1) = pk(x2, x3);
                *(uint32_t*)(Hl + o1) = pk(y2, y3);
            }
        }
}

// ---------------- combine ----------------------------------------------------
__global__ void k_combine(float* __restrict__ out, int out_size) {
    int s = blockIdx.x;
    int sl1 = g_slot1[s], sl2 = g_slot2[s];
    float g1 = (sl1 >= 0) ? g_g1[s] : 0.f;
    float g2 = (sl2 >= 0) ? g_g2[s] : 0.f;
    float dn = fmaxf(g1 + g2, 1e-9f);
    g1 /= dn; g2 /= dn;
    const float4* r1 = (sl1 >= 0)
        ? (const float4*)(g_eo + ((size_t)g_idx1[s] * CAP + sl1) * DIM) : nullptr;
    const float4* r2 = (sl2 >= 0)
        ? (const float4*)(g_eo + ((size_t)g_idx2[s] * CAP + sl2) * DIM) : nullptr;
    float4* o = (float4*)(out + (size_t)s * DIM);
    for (int j = threadIdx.x; j < DIM / 4; j += blockDim.x) {
        float4 v = make_float4(0.f, 0.f, 0.f, 0.f);
        if (r1) { float4 t = r1[j]; v.x += g1 * t.x; v.y += g1 * t.y; v.z += g1 * t.z; v.w += g1 * t.w; }
        if (r2) { float4 t = r2[j]; v.x += g2 * t.x; v.y += g2 * t.y; v.z += g2 * t.z; v.w += g2 * t.w; }
        o[j] = v;
    }
    if (s == 0) {
        size_t base = (size_t)S_TOK * DIM;
        if ((size_t)out_size > base && threadIdx.x == 0) out[base] = g_laux;
        if ((size_t)out_size >= base + 1 + NE && threadIdx.x >= 1 && threadIdx.x <= NE)
            out[base + threadIdx.x] = (float)g_count1[threadIdx.x - 1];
    }
}

// ---------------- launch -----------------------------------------------------
extern "C" void kernel_launch(void* const* d_in, const int* in_sizes, int n_in,
                              void* d_out, int out_size) {
    (void)in_sizes; (void)n_in;
    const float* x  = (const float*)d_in[0];
    const float* wg = (const float*)d_in[1];
    const float* w1 = (const float*)d_in[2];
    const float* w3 = (const float*)d_in[3];
    const float* w2 = (const float*)d_in[4];
    float* out = (float*)d_out;

    cudaFuncSetAttribute(k_gemm_f<0>, cudaFuncAttributeMaxDynamicSharedMemorySize, GSMEM);
    cudaFuncSetAttribute(k_gemm_f<1>, cudaFuncAttributeMaxDynamicSharedMemorySize, GSMEM);

    void *p_ah, *p_al, *p_w1h, *p_w1l, *p_w3h, *p_w3l, *p_w2h, *p_w2l;
    void *p_t1, *p_hh, *p_hl, *p_eo;
    cudaGetSymbolAddress(&p_ah, g_ah);   cudaGetSymbolAddress(&p_al, g_al);
    cudaGetSymbolAddress(&p_w1h, g_w1h); cudaGetSymbolAddress(&p_w1l, g_w1l);
    cudaGetSymbolAddress(&p_w3h, g_w3h); cudaGetSymbolAddress(&p_w3l, g_w3l);
    cudaGetSymbolAddress(&p_w2h, g_w2h); cudaGetSymbolAddress(&p_w2l, g_w2l);
    cudaGetSymbolAddress(&p_t1, g_t1);
    cudaGetSymbolAddress(&p_hh, g_hh);   cudaGetSymbolAddress(&p_hl, g_hl);
    cudaGetSymbolAddress(&p_eo, g_eo);

    k_init<<<(NE * CAP + 255) / 256, 256>>>();
    k_logits<<<S_TOK, 128>>>(x, wg);
    k_top2<<<S_TOK / 256, 256>>>();
    k_scan<<<1, 256>>>();
    k_dispatch_split<<<NE * CAP, 256>>>(x);

    const size_t NW4 = (size_t)NE * DIM * FF / 4;
    int wgrid = (int)((NW4 + 255) / 256);
    k_wsplit<<<wgrid, 256>>>((const float4*)w1, (uint2*)p_w1h, (uint2*)p_w1l, NW4);
    k_wsplit<<<wgrid, 256>>>((const float4*)w3, (uint2*)p_w3h, (uint2*)p_w3l, NW4);
    k_wsplit<<<wgrid, 256>>>((const float4*)w2, (uint2*)p_w2h, (uint2*)p_w2l, NW4);

    dim3 grid1(FF / 128, CAP / 128, NE);   // (43, 8, 8)
    // t1 = xe @ w1 (fp32)
    k_gemm_f<0><<<grid1, 256, GSMEM>>>((const bf16*)p_ah, (const bf16*)p_al,
                                       (const bf16*)p_w1h, (const bf16*)p_w1l,
                                       (float*)p_t1, nullptr, nullptr, nullptr,
                                       FF, DIM);
    // h = silu(t1) * (xe @ w3)  -> hh/hl bf16 split (fused epilogue)
    k_gemm_f<1><<<grid1, 256, GSMEM>>>((const bf16*)p_ah, (const bf16*)p_al,
                                       (const bf16*)p_w3h, (const bf16*)p_w3l,
                                       nullptr, (const float*)p_t1,
                                       (bf16*)p_hh, (bf16*)p_hl, FF, DIM);
    dim3 grid2(DIM / 128, CAP / 128, NE);  // (16, 8, 8)
    k_gemm_f<0><<<grid2, 256, GSMEM>>>((const bf16*)p_hh, (const bf16*)p_hl,
                                       (const bf16*)p_w2h, (const bf16*)p_w2l,
                                       (float*)p_eo, nullptr, nullptr, nullptr,
                                       DIM, FF);

    k_combine<<<S_TOK, 256>>>(out, out_size);
}

// round 6
// speedup vs baseline: 3.8945x; 1.4661x over previous
#include <cuda_runtime.h>
#include <cuda_fp16.h>
#include <cstdint>

#define S_TOK 4096
#define DIM   2048
#define NE    8
#define FF    5504
#define CAP   1024

typedef __half fp16;

// ---------------- device-global scratch ------------------------------------
__device__ float g_logits[S_TOK * NE];
__device__ int   g_idx1[S_TOK], g_idx2[S_TOK];
__device__ float g_g1[S_TOK], g_g2[S_TOK];
__device__ int   g_slot1[S_TOK], g_slot2[S_TOK];
__device__ int   g_tok4slot[NE * CAP];
__device__ int   g_count1[NE];
__device__ float g_me[NE];
__device__ float g_laux;

__device__ fp16  g_ah[(size_t)NE * CAP * DIM];    // 33.5MB each
__device__ fp16  g_al[(size_t)NE * CAP * DIM];
__device__ fp16  g_w1h[(size_t)NE * DIM * FF];    // 180MB each (single fp16)
__device__ fp16  g_w3h[(size_t)NE * DIM * FF];
__device__ fp16  g_w2h[(size_t)NE * FF * DIM];
__device__ float g_t1[(size_t)NE * CAP * FF];     // 180MB
__device__ fp16  g_hh[(size_t)NE * CAP * FF];     // 90MB each
__device__ fp16  g_hl[(size_t)NE * CAP * FF];
__device__ float g_eo[(size_t)NE * CAP * DIM];    // 64MB

// ---------------- helpers ----------------------------------------------------
__device__ __forceinline__ uint32_t smem_to_u32(const void* p) {
    uint32_t a;
    asm("{ .reg .u64 t; cvta.to.shared.u64 t, %1; cvt.u32.u64 %0, t; }"
        : "=r"(a) : "l"(p));
    return a;
}
__device__ __forceinline__ void cpasync16(uint32_t dst, const void* src) {
    asm volatile("cp.async.cg.shared.global [%0], [%1], 16;" :: "r"(dst), "l"(src));
}
#define CP_COMMIT() asm volatile("cp.async.commit_group;" ::: "memory")
#define CP_WAIT1()  asm volatile("cp.async.wait_group 1;" ::: "memory")
#define CP_WAIT0()  asm volatile("cp.async.wait_group 0;" ::: "memory")

__device__ __forceinline__ void ldsm_x4(uint32_t& r0, uint32_t& r1, uint32_t& r2,
                                        uint32_t& r3, uint32_t a) {
    asm volatile("ldmatrix.sync.aligned.m8n8.x4.shared.b16 {%0,%1,%2,%3}, [%4];"
                 : "=r"(r0), "=r"(r1), "=r"(r2), "=r"(r3) : "r"(a));
}
__device__ __forceinline__ void ldsm_x4t(uint32_t& r0, uint32_t& r1, uint32_t& r2,
                                         uint32_t& r3, uint32_t a) {
    asm volatile("ldmatrix.sync.aligned.m8n8.x4.trans.shared.b16 {%0,%1,%2,%3}, [%4];"
                 : "=r"(r0), "=r"(r1), "=r"(r2), "=r"(r3) : "r"(a));
}
__device__ __forceinline__ void mma16816(float* c, const uint32_t* a,
                                         uint32_t b0, uint32_t b1) {
    asm volatile("mma.sync.aligned.m16n8k16.row.col.f32.f16.f16.f32 "
                 "{%0,%1,%2,%3},{%4,%5,%6,%7},{%8,%9},{%0,%1,%2,%3};"
                 : "+f"(c[0]), "+f"(c[1]), "+f"(c[2]), "+f"(c[3])
                 : "r"(a[0]), "r"(a[1]), "r"(a[2]), "r"(a[3]), "r"(b0), "r"(b1));
}
__device__ __forceinline__ uint32_t pkh(fp16 a, fp16 b) {
    return (uint32_t)__half_as_ushort(a) | ((uint32_t)__half_as_ushort(b) << 16);
}
__device__ __forceinline__ void split2h(float v, fp16& h, fp16& l) {
    h = __float2half_rn(v);
    l = __float2half_rn(v - __half2float(h));
}

// ---------------- gating ------------------------------------------------------
__global__ void k_init() {
    int i = blockIdx.x * blockDim.x + threadIdx.x;
    if (i < NE * CAP) g_tok4slot[i] = -1;
    if (i < NE) g_me[i] = 0.f;
}
__global__ void k_logits(const float* __restrict__ x, const float* __restrict__ wg) {
    int s = blockIdx.x;
    float acc[NE];
#pragma unroll
    for (int e = 0; e < NE; e++) acc[e] = 0.f;
    const float* xr = x + (size_t)s * DIM;
    for (int j = threadIdx.x; j < DIM; j += blockDim.x) {
        float xv = xr[j];
        float4 w0 = *(const float4*)(wg + (size_t)j * NE);
        float4 w1v = *(const float4*)(wg + (size_t)j * NE + 4);
        acc[0] += xv * w0.x;  acc[1] += xv * w0.y;
        acc[2] += xv * w0.z;  acc[3] += xv * w0.w;
        acc[4] += xv * w1v.x; acc[5] += xv * w1v.y;
        acc[6] += xv * w1v.z; acc[7] += xv * w1v.w;
    }
#pragma unroll
    for (int off = 16; off; off >>= 1)
#pragma unroll
        for (int e = 0; e < NE; e++)
            acc[e] += __shfl_down_sync(0xffffffffu, acc[e], off);
    __shared__ float red[4][NE];
    int lane = threadIdx.x & 31, wp = threadIdx.x >> 5;
    if (lane == 0)
#pragma unroll
        for (int e = 0; e < NE; e++) red[wp][e] = acc[e];
    __syncthreads();
    if (threadIdx.x < NE)
        g_logits[(size_t)s * NE + threadIdx.x] =
            red[0][threadIdx.x] + red[1][threadIdx.x] +
            red[2][threadIdx.x] + red[3][threadIdx.x];
}
__global__ void k_top2() {
    __shared__ float sme[NE];
    if (threadIdx.x < NE) sme[threadIdx.x] = 0.f;
    __syncthreads();
    int s = blockIdx.x * blockDim.x + threadIdx.x;
    float l[NE];
    float4 a = *(const float4*)(g_logits + (size_t)s * NE);
    float4 b = *(const float4*)(g_logits + (size_t)s * NE + 4);
    l[0]=a.x; l[1]=a.y; l[2]=a.z; l[3]=a.w; l[4]=b.x; l[5]=b.y; l[6]=b.z; l[7]=b.w;
    float mx = l[0];
#pragma unroll
    for (int e = 1; e < NE; e++) mx = fmaxf(mx, l[e]);
    float g[NE], sum = 0.f;
#pragma unroll
    for (int e = 0; e < NE; e++) { g[e] = __expf(l[e] - mx); sum += g[e]; }
    float inv = 1.f / sum;
    int i1 = 0; float b1 = l[0];
#pragma unroll
    for (int e = 1; e < NE; e++) if (l[e] > b1) { b1 = l[e]; i1 = e; }
    int i2 = 0; float b2 = -3.0e38f;
#pragma unroll
    for (int e = 0; e < NE; e++) if (e != i1 && l[e] > b2) { b2 = l[e]; i2 = e; }
    g_idx1[s] = i1; g_idx2[s] = i2;
    g_g1[s] = g[i1] * inv; g_g2[s] = g[i2] * inv;
#pragma unroll
    for (int e = 0; e < NE; e++) atomicAdd(&sme[e], g[e] * inv);
    __syncthreads();
    if (threadIdx.x < NE) atomicAdd(&g_me[threadIdx.x], sme[threadIdx.x]);
}
__global__ void k_scan() {
    __shared__ int si1[S_TOK], si2[S_TOK];
    int tid = threadIdx.x;
    for (int i = tid; i < S_TOK; i += blockDim.x) { si1[i] = g_idx1[i]; si2[i] = g_idx2[i]; }
    __syncthreads();
    int lane = tid & 31, e = tid >> 5;
    unsigned lm = (1u << lane) - 1u;
    if (e < NE) {
        int c1 = 0;
        for (int s0 = 0; s0 < S_TOK; s0 += 32) {
            int s = s0 + lane;
            int m = (si1[s] == e);
            unsigned bal = __ballot_sync(0xffffffffu, m);
            if (m) {
                int pos = c1 + __popc(bal & lm);
                if (pos < CAP) { g_slot1[s] = pos; g_tok4slot[e * CAP + pos] = s; }
                else g_slot1[s] = -1;
            }
            c1 += __popc(bal);
        }
        if (lane == 0) g_count1[e] = c1;
        int c2 = c1;
        for (int s0 = 0; s0 < S_TOK; s0 += 32) {
            int s = s0 + lane;
            int m = (si2[s] == e);
            unsigned bal = __ballot_sync(0xffffffffu, m);
            if (m) {
                int pos = c2 + __popc(bal & lm);
                if (pos < CAP) { g_slot2[s] = pos; g_tok4slot[e * CAP + pos] = s; }
                else g_slot2[s] = -1;
            }
            c2 += __popc(bal);
        }
    }
    __syncthreads();
    if (tid == 0) {
        float acc = 0.f;
        for (int i = 0; i < NE; i++)
            acc += (g_me[i] / (float)S_TOK) * ((float)g_count1[i] / (float)S_TOK);
        g_laux = acc * (float)NE;
    }
}

// ---------------- dispatch: gather token rows -> Ah/Al fp16 -----------------
__global__ void k_dispatch_split(const float* __restrict__ x) {
    int slot = blockIdx.x;
    int s = g_tok4slot[slot];
    uint2* ah = (uint2*)(g_ah + (size_t)slot * DIM);
    uint2* al = (uint2*)(g_al + (size_t)slot * DIM);
    if (s >= 0) {
        const float4* xr = (const float4*)(x + (size_t)s * DIM);
        for (int j = threadIdx.x; j < DIM / 4; j += blockDim.x) {
            float4 v = xr[j];
            fp16 h0, l0, h1, l1, h2, l2, h3, l3;
            split2h(v.x, h0, l0); split2h(v.y, h1, l1);
            split2h(v.z, h2, l2); split2h(v.w, h3, l3);
            ah[j] = make_uint2(pkh(h0, h1), pkh(h2, h3));
            al[j] = make_uint2(pkh(l0, l1), pkh(l2, l3));
        }
    } else {
        uint2 z = make_uint2(0u, 0u);
        for (int j = threadIdx.x; j < DIM / 4; j += blockDim.x) { ah[j] = z; al[j] = z; }
    }
}

// ---------------- weight convert: fp32 -> single fp16 -----------------------
__global__ void k_wcvt(const float4* __restrict__ src, uint2* __restrict__ hh, size_t n4) {
    size_t i = (size_t)blockIdx.x * blockDim.x + threadIdx.x;
    if (i >= n4) return;
    float4 v = src[i];
    hh[i] = make_uint2(pkh(__float2half_rn(v.x), __float2half_rn(v.y)),
                       pkh(__float2half_rn(v.z), __float2half_rn(v.w)));
}

// ---------------- fp16 2-term HMMA GEMM: C = (Ah+Al) @ Bh -------------------
// EPI 0: write fp32 C.  EPI 1: read Aux(t1), h=silu(aux)*acc -> hh/hl fp16.
#define ASTRIDE 80u
#define BSTRIDE 272u
#define A_SZ    (128u * ASTRIDE)          // 10240
#define B_SZ    (32u * BSTRIDE)           // 8704
#define OFF_AH  0u
#define OFF_AL  A_SZ
#define OFF_B   (2u * A_SZ)
#define STG     (2u * A_SZ + B_SZ)        // 29184
#define NSTAGE  3
#define GSMEM   (NSTAGE * STG)            // 87552

template <int EPI>
__global__ void __launch_bounds__(256, 2)
k_gemm_f(const fp16* __restrict__ Ahg, const fp16* __restrict__ Alg,
         const fp16* __restrict__ Bhg,
         float* __restrict__ Cg, const float* __restrict__ Auxg,
         fp16* __restrict__ Hh, fp16* __restrict__ Hl, int N, int K) {
    extern __shared__ __align__(16) uint8_t smem[];
    const int M = CAP;
    int tid = threadIdx.x, lane = tid & 31, wid = tid >> 5;
    int wm = wid & 1, wn = wid >> 1;
    int n0 = blockIdx.x * 128, m0 = blockIdx.y * 128, e = blockIdx.z;
    const fp16* A0 = Ahg + (size_t)e * M * K;
    const fp16* A1 = Alg + (size_t)e * M * K;
    const fp16* B0 = Bhg + (size_t)e * K * N;
    const int NIT = K / 32;
    uint32_t sb = smem_to_u32(smem);

    float acc[4][4][4];
#pragma unroll
    for (int a = 0; a < 4; a++)
#pragma unroll
        for (int b = 0; b < 4; b++)
#pragma unroll
            for (int c = 0; c < 4; c++) acc[a][b][c] = 0.f;

    auto load_stage = [&](int kc, int slot) {
        uint32_t st = sb + (uint32_t)slot * STG;
#pragma unroll
        for (int j = 0; j < 2; j++) {
            int id = tid + j * 256;
            int row = id >> 2, c = id & 3;
            const size_t ga = (size_t)(m0 + row) * K + kc * 32 + c * 8;
            cpasync16(st + OFF_AH + (uint32_t)row * ASTRIDE + c * 16, A0 + ga);
            cpasync16(st + OFF_AL + (uint32_t)row * ASTRIDE + c * 16, A1 + ga);
        }
#pragma unroll
        for (int j = 0; j < 2; j++) {
            int id = tid + j * 256;
            int k = id >> 4, c = id & 15;
            const size_t gb = (size_t)(kc * 32 + k) * N + n0 + c * 8;
            cpasync16(st + OFF_B + (uint32_t)k * BSTRIDE + c * 16, B0 + gb);
        }
    };

    // per-lane ldmatrix offsets (proven layout)
    int mm = lane >> 3;
    int rowin = (mm & 1) * 8 + (lane & 7);
    int c0 = mm >> 1;
    uint32_t aOff = (uint32_t)(wm * 64 + rowin) * ASTRIDE + (uint32_t)c0 * 16;
    int p = lane >> 4, mrow = (lane >> 3) & 1;
    int kin = mrow * 8 + (lane & 7);
    uint32_t bOff = (uint32_t)kin * BSTRIDE + (uint32_t)(wn * 4 + p) * 16;

    load_stage(0, 0); CP_COMMIT();
    load_stage(1, 1); CP_COMMIT();
    for (int i = 0; i < NIT; i++) {
        if (i + 1 < NIT) CP_WAIT1(); else CP_WAIT0();
        __syncthreads();
        uint32_t st = sb + (uint32_t)(i % NSTAGE) * STG;
#pragma unroll
        for (int s = 0; s < 2; s++) {
            uint32_t a[4][4], bh[2][4];
#pragma unroll
            for (int mt = 0; mt < 4; mt++)
                ldsm_x4(a[mt][0], a[mt][1], a[mt][2], a[mt][3],
                        st + OFF_AH + aOff + (uint32_t)mt * (16u * ASTRIDE) + (uint32_t)s * 32);
            ldsm_x4t(bh[0][0], bh[0][1], bh[0][2], bh[0][3],
                     st + OFF_B + bOff + (uint32_t)s * (16u * BSTRIDE));
            ldsm_x4t(bh[1][0], bh[1][1], bh[1][2], bh[1][3],
                     st + OFF_B + bOff + (uint32_t)s * (16u * BSTRIDE) + 32u);
#pragma unroll
            for (int mt = 0; mt < 4; mt++)
#pragma unroll
                for (int nt = 0; nt < 4; nt++)
                    mma16816(acc[mt][nt], a[mt], bh[nt >> 1][(nt & 1) * 2],
                             bh[nt >> 1][(nt & 1) * 2 + 1]);
#pragma unroll
            for (int mt = 0; mt < 4; mt++)
                ldsm_x4(a[mt][0], a[mt][1], a[mt][2], a[mt][3],
                        st + OFF_AL + aOff + (uint32_t)mt * (16u * ASTRIDE) + (uint32_t)s * 32);
#pragma unroll
            for (int mt = 0; mt < 4; mt++)
#pragma unroll
                for (int nt = 0; nt < 4; nt++)
                    mma16816(acc[mt][nt], a[mt], bh[nt >> 1][(nt & 1) * 2],
                             bh[nt >> 1][(nt & 1) * 2 + 1]);
        }
        if (i + 2 < NIT) { load_stage(i + 2, (i + 2) % NSTAGE); CP_COMMIT(); }
    }

    int rg = lane >> 2, cgi = (lane & 3) * 2;
    size_t ebase = (size_t)e * M * N;
#pragma unroll
    for (int mt = 0; mt < 4; mt++)
#pragma unroll
        for (int nt = 0; nt < 4; nt++) {
            int row = m0 + wm * 64 + mt * 16 + rg;
            int col = n0 + wn * 32 + nt * 8 + cgi;
            size_t o0 = ebase + (size_t)row * N + col;
            size_t o1 = ebase + (size_t)(row + 8) * N + col;
            if (EPI == 0) {
                *(float2*)(Cg + o0) = make_float2(acc[mt][nt][0], acc[mt][nt][1]);
                *(float2*)(Cg + o1) = make_float2(acc[mt][nt][2], acc[mt][nt][3]);
            } else {
                float2 t0 = *(const float2*)(Auxg + o0);
                float2 t1 = *(const float2*)(Auxg + o1);
                float h0 = t0.x / (1.f + __expf(-t0.x)) * acc[mt][nt][0];
                float h1 = t0.y / (1.f + __expf(-t0.y)) * acc[mt][nt][1];
                float h2 = t1.x / (1.f + __expf(-t1.x)) * acc[mt][nt][2];
                float h3 = t1.y / (1.f + __expf(-t1.y)) * acc[mt][nt][3];
                fp16 x0, y0, x1, y1, x2, y2, x3, y3;
                split2h(h0, x0, y0); split2h(h1, x1, y1);
                split2h(h2, x2, y2); split2h(h3, x3, y3);
                *(uint32_t*)(Hh + o0) = pkh(x0, x1);
                *(uint32_t*)(Hl + o0) = pkh(y0, y1);
                *(uint32_t*)(Hh + o1) = pkh(x2, x3);
                *(uint32_t*)(Hl + o1) = pkh(y2, y3);
            }
        }
}

// ---------------- combine ----------------------------------------------------
__global__ void k_combine(float* __restrict__ out, int out_size) {
    int s = blockIdx.x;
    int sl1 = g_slot1[s], sl2 = g_slot2[s];
    float g1 = (sl1 >= 0) ? g_g1[s] : 0.f;
    float g2 = (sl2 >= 0) ? g_g2[s] : 0.f;
    float dn = fmaxf(g1 + g2, 1e-9f);
    g1 /= dn; g2 /= dn;
    const float4* r1 = (sl1 >= 0)
        ? (const float4*)(g_eo + ((size_t)g_idx1[s] * CAP + sl1) * DIM) : nullptr;
    const float4* r2 = (sl2 >= 0)
        ? (const float4*)(g_eo + ((size_t)g_idx2[s] * CAP + sl2) * DIM) : nullptr;
    float4* o = (float4*)(out + (size_t)s * DIM);
    for (int j = threadIdx.x; j < DIM / 4; j += blockDim.x) {
        float4 v = make_float4(0.f, 0.f, 0.f, 0.f);
        if (r1) { float4 t = r1[j]; v.x += g1 * t.x; v.y += g1 * t.y; v.z += g1 * t.z; v.w += g1 * t.w; }
        if (r2) { float4 t = r2[j]; v.x += g2 * t.x; v.y += g2 * t.y; v.z += g2 * t.z; v.w += g2 * t.w; }
        o[j] = v;
    }
    if (s == 0) {
        size_t base = (size_t)S_TOK * DIM;
        if ((size_t)out_size > base && threadIdx.x == 0) out[base] = g_laux;
        if ((size_t)out_size >= base + 1 + NE && threadIdx.x >= 1 && threadIdx.x <= NE)
            out[base + threadIdx.x] = (float)g_count1[threadIdx.x - 1];
    }
}

// ---------------- launch -----------------------------------------------------
extern "C" void kernel_launch(void* const* d_in, const int* in_sizes, int n_in,
                              void* d_out, int out_size) {
    (void)in_sizes; (void)n_in;
    const float* x  = (const float*)d_in[0];
    const float* wg = (const float*)d_in[1];
    const float* w1 = (const float*)d_in[2];
    const float* w3 = (const float*)d_in[3];
    const float* w2 = (const float*)d_in[4];
    float* out = (float*)d_out;

    cudaFuncSetAttribute(k_gemm_f<0>, cudaFuncAttributeMaxDynamicSharedMemorySize, GSMEM);
    cudaFuncSetAttribute(k_gemm_f<1>, cudaFuncAttributeMaxDynamicSharedMemorySize, GSMEM);

    void *p_ah, *p_al, *p_w1h, *p_w3h, *p_w2h, *p_t1, *p_hh, *p_hl, *p_eo;
    cudaGetSymbolAddress(&p_ah, g_ah);   cudaGetSymbolAddress(&p_al, g_al);
    cudaGetSymbolAddress(&p_w1h, g_w1h); cudaGetSymbolAddress(&p_w3h, g_w3h);
    cudaGetSymbolAddress(&p_w2h, g_w2h); cudaGetSymbolAddress(&p_t1, g_t1);
    cudaGetSymbolAddress(&p_hh, g_hh);   cudaGetSymbolAddress(&p_hl, g_hl);
    cudaGetSymbolAddress(&p_eo, g_eo);

    k_init<<<(NE * CAP + 255) / 256, 256>>>();
    k_logits<<<S_TOK, 128>>>(x, wg);
    k_top2<<<S_TOK / 256, 256>>>();
    k_scan<<<1, 256>>>();
    k_dispatch_split<<<NE * CAP, 256>>>(x);

    const size_t NW4 = (size_t)NE * DIM * FF / 4;
    int wgrid = (int)((NW4 + 255) / 256);
    k_wcvt<<<wgrid, 256>>>((const float4*)w1, (uint2*)p_w1h, NW4);
    k_wcvt<<<wgrid, 256>>>((const float4*)w3, (uint2*)p_w3h, NW4);
    k_wcvt<<<wgrid, 256>>>((const float4*)w2, (uint2*)p_w2h, NW4);

    dim3 grid1(FF / 128, CAP / 128, NE);   // (43, 8, 8)
    // t1 = xe @ w1 (fp32)
    k_gemm_f<0><<<grid1, 256, GSMEM>>>((const fp16*)p_ah, (const fp16*)p_al,
                                       (const fp16*)p_w1h,
                                       (float*)p_t1, nullptr, nullptr, nullptr,
                                       FF, DIM);
    // h = silu(t1) * (xe @ w3)  -> hh/hl fp16 split (fused epilogue)
    k_gemm_f<1><<<grid1, 256, GSMEM>>>((const fp16*)p_ah, (const fp16*)p_al,
                                       (const fp16*)p_w3h,
                                       nullptr, (const float*)p_t1,
                                       (fp16*)p_hh, (fp16*)p_hl, FF, DIM);
    dim3 grid2(DIM / 128, CAP / 128, NE);  // (16, 8, 8)
    k_gemm_f<0><<<grid2, 256, GSMEM>>>((const fp16*)p_hh, (const fp16*)p_hl,
                                       (const fp16*)p_w2h,
                                       (float*)p_eo, nullptr, nullptr, nullptr,
                                       DIM, FF);

    k_combine<<<S_TOK, 256>>>(out, out_size);
}

// round 7
// speedup vs baseline: 6.3442x; 1.6290x over previous
#include <cuda_runtime.h>
#include <cuda_fp16.h>
#include <cstdint>

#define S_TOK 4096
#define DIM   2048
#define NE    8
#define FF    5504
#define CAP   1024

typedef __half fp16;

// ---------------- device-global scratch ------------------------------------
__device__ float g_logits[S_TOK * NE];
__device__ int   g_idx1[S_TOK], g_idx2[S_TOK];
__device__ float g_g1[S_TOK], g_g2[S_TOK];
__device__ int   g_slot1[S_TOK], g_slot2[S_TOK];
__device__ int   g_tok4slot[NE * CAP];
__device__ int   g_count1[NE];
__device__ float g_me[NE];
__device__ float g_laux;

__device__ fp16  g_ah[(size_t)NE * CAP * DIM];    // 33.5MB
__device__ fp16  g_w1h[(size_t)NE * DIM * FF];    // 180MB each
__device__ fp16  g_w3h[(size_t)NE * DIM * FF];
__device__ fp16  g_w2h[(size_t)NE * FF * DIM];
__device__ float g_t1[(size_t)NE * CAP * FF];     // 180MB
__device__ fp16  g_hh[(size_t)NE * CAP * FF];     // 90MB
__device__ float g_eo[(size_t)NE * CAP * DIM];    // 64MB

// ---------------- helpers ----------------------------------------------------
__device__ __forceinline__ uint32_t smem_to_u32(const void* p) {
    uint32_t a;
    asm("{ .reg .u64 t; cvta.to.shared.u64 t, %1; cvt.u32.u64 %0, t; }"
        : "=r"(a) : "l"(p));
    return a;
}
__device__ __forceinline__ void cpasync16(uint32_t dst, const void* src) {
    asm volatile("cp.async.cg.shared.global [%0], [%1], 16;" :: "r"(dst), "l"(src));
}
#define CP_COMMIT() asm volatile("cp.async.commit_group;" ::: "memory")
#define CP_WAIT2()  asm volatile("cp.async.wait_group 2;" ::: "memory")

__device__ __forceinline__ void ldsm_x4(uint32_t& r0, uint32_t& r1, uint32_t& r2,
                                        uint32_t& r3, uint32_t a) {
    asm volatile("ldmatrix.sync.aligned.m8n8.x4.shared.b16 {%0,%1,%2,%3}, [%4];"
                 : "=r"(r0), "=r"(r1), "=r"(r2), "=r"(r3) : "r"(a));
}
__device__ __forceinline__ void ldsm_x4t(uint32_t& r0, uint32_t& r1, uint32_t& r2,
                                         uint32_t& r3, uint32_t a) {
    asm volatile("ldmatrix.sync.aligned.m8n8.x4.trans.shared.b16 {%0,%1,%2,%3}, [%4];"
                 : "=r"(r0), "=r"(r1), "=r"(r2), "=r"(r3) : "r"(a));
}
__device__ __forceinline__ void mma16816(float* c, const uint32_t* a,
                                         uint32_t b0, uint32_t b1) {
    asm volatile("mma.sync.aligned.m16n8k16.row.col.f32.f16.f16.f32 "
                 "{%0,%1,%2,%3},{%4,%5,%6,%7},{%8,%9},{%0,%1,%2,%3};"
                 : "+f"(c[0]), "+f"(c[1]), "+f"(c[2]), "+f"(c[3])
                 : "r"(a[0]), "r"(a[1]), "r"(a[2]), "r"(a[3]), "r"(b0), "r"(b1));
}
__device__ __forceinline__ uint32_t pkh(fp16 a, fp16 b) {
    return (uint32_t)__half_as_ushort(a) | ((uint32_t)__half_as_ushort(b) << 16);
}

// ---------------- gating ------------------------------------------------------
__global__ void k_init() {
    int i = blockIdx.x * blockDim.x + threadIdx.x;
    if (i < NE * CAP) g_tok4slot[i] = -1;
    if (i < NE) g_me[i] = 0.f;
}
__global__ void k_logits(const float* __restrict__ x, const float* __restrict__ wg) {
    int s = blockIdx.x;
    float acc[NE];
#pragma unroll
    for (int e = 0; e < NE; e++) acc[e] = 0.f;
    const float* xr = x + (size_t)s * DIM;
    for (int j = threadIdx.x; j < DIM; j += blockDim.x) {
        float xv = xr[j];
        float4 w0 = *(const float4*)(wg + (size_t)j * NE);
        float4 w1v = *(const float4*)(wg + (size_t)j * NE + 4);
        acc[0] += xv * w0.x;  acc[1] += xv * w0.y;
        acc[2] += xv * w0.z;  acc[3] += xv * w0.w;
        acc[4] += xv * w1v.x; acc[5] += xv * w1v.y;
        acc[6] += xv * w1v.z; acc[7] += xv * w1v.w;
    }
#pragma unroll
    for (int off = 16; off; off >>= 1)
#pragma unroll
        for (int e = 0; e < NE; e++)
            acc[e] += __shfl_down_sync(0xffffffffu, acc[e], off);
    __shared__ float red[4][NE];
    int lane = threadIdx.x & 31, wp = threadIdx.x >> 5;
    if (lane == 0)
#pragma unroll
        for (int e = 0; e < NE; e++) red[wp][e] = acc[e];
    __syncthreads();
    if (threadIdx.x < NE)
        g_logits[(size_t)s * NE + threadIdx.x] =
            red[0][threadIdx.x] + red[1][threadIdx.x] +
            red[2][threadIdx.x] + red[3][threadIdx.x];
}
__global__ void k_top2() {
    __shared__ float sme[NE];
    if (threadIdx.x < NE) sme[threadIdx.x] = 0.f;
    __syncthreads();
    int s = blockIdx.x * blockDim.x + threadIdx.x;
    float l[NE];
    float4 a = *(const float4*)(g_logits + (size_t)s * NE);
    float4 b = *(const float4*)(g_logits + (size_t)s * NE + 4);
    l[0]=a.x; l[1]=a.y; l[2]=a.z; l[3]=a.w; l[4]=b.x; l[5]=b.y; l[6]=b.z; l[7]=b.w;
    float mx = l[0];
#pragma unroll
    for (int e = 1; e < NE; e++) mx = fmaxf(mx, l[e]);
    float g[NE], sum = 0.f;
#pragma unroll
    for (int e = 0; e < NE; e++) { g[e] = __expf(l[e] - mx); sum += g[e]; }
    float inv = 1.f / sum;
    int i1 = 0; float b1 = l[0];
#pragma unroll
    for (int e = 1; e < NE; e++) if (l[e] > b1) { b1 = l[e]; i1 = e; }
    int i2 = 0; float b2 = -3.0e38f;
#pragma unroll
    for (int e = 0; e < NE; e++) if (e != i1 && l[e] > b2) { b2 = l[e]; i2 = e; }
    g_idx1[s] = i1; g_idx2[s] = i2;
    g_g1[s] = g[i1] * inv; g_g2[s] = g[i2] * inv;
#pragma unroll
    for (int e = 0; e < NE; e++) atomicAdd(&sme[e], g[e] * inv);
    __syncthreads();
    if (threadIdx.x < NE) atomicAdd(&g_me[threadIdx.x], sme[threadIdx.x]);
}
__global__ void k_scan() {
    __shared__ int si1[S_TOK], si2[S_TOK];
    int tid = threadIdx.x;
    for (int i = tid; i < S_TOK; i += blockDim.x) { si1[i] = g_idx1[i]; si2[i] = g_idx2[i]; }
    __syncthreads();
    int lane = tid & 31, e = tid >> 5;
    unsigned lm = (1u << lane) - 1u;
    if (e < NE) {
        int c1 = 0;
        for (int s0 = 0; s0 < S_TOK; s0 += 32) {
            int s = s0 + lane;
            int m = (si1[s] == e);
            unsigned bal = __ballot_sync(0xffffffffu, m);
            if (m) {
                int pos = c1 + __popc(bal & lm);
                if (pos < CAP) { g_slot1[s] = pos; g_tok4slot[e * CAP + pos] = s; }
                else g_slot1[s] = -1;
            }
            c1 += __popc(bal);
        }
        if (lane == 0) g_count1[e] = c1;
        int c2 = c1;
        for (int s0 = 0; s0 < S_TOK; s0 += 32) {
            int s = s0 + lane;
            int m = (si2[s] == e);
            unsigned bal = __ballot_sync(0xffffffffu, m);
            if (m) {
                int pos = c2 + __popc(bal & lm);
                if (pos < CAP) { g_slot2[s] = pos; g_tok4slot[e * CAP + pos] = s; }
                else g_slot2[s] = -1;
            }
            c2 += __popc(bal);
        }
    }
    __syncthreads();
    if (tid == 0) {
        float acc = 0.f;
        for (int i = 0; i < NE; i++)
            acc += (g_me[i] / (float)S_TOK) * ((float)g_count1[i] / (float)S_TOK);
        g_laux = acc * (float)NE;
    }
}

// ---------------- dispatch: gather token rows -> A fp16 ---------------------
__global__ void k_dispatch_h(const float* __restrict__ x) {
    int slot = blockIdx.x;
    int s = g_tok4slot[slot];
    uint2* ah = (uint2*)(g_ah + (size_t)slot * DIM);
    if (s >= 0) {
        const float4* xr = (const float4*)(x + (size_t)s * DIM);
        for (int j = threadIdx.x; j < DIM / 4; j += blockDim.x) {
            float4 v = xr[j];
            ah[j] = make_uint2(pkh(__float2half_rn(v.x), __float2half_rn(v.y)),
                               pkh(__float2half_rn(v.z), __float2half_rn(v.w)));
        }
    } else {
        uint2 z = make_uint2(0u, 0u);
        for (int j = threadIdx.x; j < DIM / 4; j += blockDim.x) ah[j] = z;
    }
}

// ---------------- weight convert: fp32 -> fp16 ------------------------------
__global__ void k_wcvt(const float4* __restrict__ src, uint2* __restrict__ hh, size_t n4) {
    size_t i = (size_t)blockIdx.x * blockDim.x + threadIdx.x;
    if (i >= n4) return;
    float4 v = src[i];
    hh[i] = make_uint2(pkh(__float2half_rn(v.x), __float2half_rn(v.y)),
                       pkh(__float2half_rn(v.z), __float2half_rn(v.w)));
}

// ---------------- fp16 HMMA GEMM: C = A @ B ---------------------------------
// EPI 0: write fp32 C.  EPI 1: read Aux(t1), h=silu(aux)*acc -> fp16 Hh.
#define ASTRIDE 80u
#define BSTRIDE 272u
#define A_SZ    (128u * ASTRIDE)          // 10240
#define B_SZ    (32u * BSTRIDE)           // 8704
#define OFF_B   A_SZ
#define STG     (A_SZ + B_SZ)             // 18944
#define NSTAGE  4
#define GSMEM   (NSTAGE * STG)            // 75776

template <int EPI>
__global__ void __launch_bounds__(256, 2)
k_gemm_f(const fp16* __restrict__ Ag, const fp16* __restrict__ Bg,
         float* __restrict__ Cg, const float* __restrict__ Auxg,
         fp16* __restrict__ Hh, int N, int K) {
    extern __shared__ __align__(16) uint8_t smem[];
    const int M = CAP;
    int tid = threadIdx.x, lane = tid & 31, wid = tid >> 5;
    int wm = wid & 1, wn = wid >> 1;
    int n0 = blockIdx.x * 128, m0 = blockIdx.y * 128, e = blockIdx.z;
    const fp16* A0 = Ag + (size_t)e * M * K;
    const fp16* B0 = Bg + (size_t)e * K * N;
    const int NIT = K / 32;
    uint32_t sb = smem_to_u32(smem);

    float acc[4][4][4];
#pragma unroll
    for (int a = 0; a < 4; a++)
#pragma unroll
        for (int b = 0; b < 4; b++)
#pragma unroll
            for (int c = 0; c < 4; c++) acc[a][b][c] = 0.f;

    auto load_stage = [&](int kc, int slot) {
        uint32_t st = sb + (uint32_t)slot * STG;
#pragma unroll
        for (int j = 0; j < 2; j++) {
            int id = tid + j * 256;
            int row = id >> 2, c = id & 3;
            cpasync16(st + (uint32_t)row * ASTRIDE + c * 16,
                      A0 + (size_t)(m0 + row) * K + kc * 32 + c * 8);
        }
#pragma unroll
        for (int j = 0; j < 2; j++) {
            int id = tid + j * 256;
            int k = id >> 4, c = id & 15;
            cpasync16(st + OFF_B + (uint32_t)k * BSTRIDE + c * 16,
                      B0 + (size_t)(kc * 32 + k) * N + n0 + c * 8);
        }
    };

    // per-lane ldmatrix offsets (proven layout)
    int mm = lane >> 3;
    int rowin = (mm & 1) * 8 + (lane & 7);
    int c0 = mm >> 1;
    uint32_t aOff = (uint32_t)(wm * 64 + rowin) * ASTRIDE + (uint32_t)c0 * 16;
    int p = lane >> 4, mrow = (lane >> 3) & 1;
    int kin = mrow * 8 + (lane & 7);
    uint32_t bOff = (uint32_t)kin * BSTRIDE + (uint32_t)(wn * 4 + p) * 16;

    load_stage(0, 0); CP_COMMIT();
    load_stage(1, 1); CP_COMMIT();
    load_stage(2, 2); CP_COMMIT();
    for (int i = 0; i < NIT; i++) {
        CP_WAIT2();
        __syncthreads();
        uint32_t st = sb + (uint32_t)(i % NSTAGE) * STG;
#pragma unroll
        for (int s = 0; s < 2; s++) {
            uint32_t a[4][4], bh[2][4];
#pragma unroll
            for (int mt = 0; mt < 4; mt++)
                ldsm_x4(a[mt][0], a[mt][1], a[mt][2], a[mt][3],
                        st + aOff + (uint32_t)mt * (16u * ASTRIDE) + (uint32_t)s * 32);
            ldsm_x4t(bh[0][0], bh[0][1], bh[0][2], bh[0][3],
                     st + OFF_B + bOff + (uint32_t)s * (16u * BSTRIDE));
            ldsm_x4t(bh[1][0], bh[1][1], bh[1][2], bh[1][3],
                     st + OFF_B + bOff + (uint32_t)s * (16u * BSTRIDE) + 32u);
#pragma unroll
            for (int mt = 0; mt < 4; mt++)
#pragma unroll
                for (int nt = 0; nt < 4; nt++)
                    mma16816(acc[mt][nt], a[mt], bh[nt >> 1][(nt & 1) * 2],
                             bh[nt >> 1][(nt & 1) * 2 + 1]);
        }
        if (i + 3 < NIT) load_stage(i + 3, (i + 3) % NSTAGE);
        CP_COMMIT();   // always commit: keeps wait_group accounting exact
    }

    int rg = lane >> 2, cgi = (lane & 3) * 2;
    size_t ebase = (size_t)e * M * N;
#pragma unroll
    for (int mt = 0; mt < 4; mt++)
#pragma unroll
        for (int nt = 0; nt < 4; nt++) {
            int row = m0 + wm * 64 + mt * 16 + rg;
            int col = n0 + wn * 32 + nt * 8 + cgi;
            size_t o0 = ebase + (size_t)row * N + col;
            size_t o1 = ebase + (size_t)(row + 8) * N + col;
            if (EPI == 0) {
                *(float2*)(Cg + o0) = make_float2(acc[mt][nt][0], acc[mt][nt][1]);
                *(float2*)(Cg + o1) = make_float2(acc[mt][nt][2], acc[mt][nt][3]);
            } else {
                float2 t0 = *(const float2*)(Auxg + o0);
                float2 t1 = *(const float2*)(Auxg + o1);
                float h0 = t0.x / (1.f + __expf(-t0.x)) * acc[mt][nt][0];
                float h1 = t0.y / (1.f + __expf(-t0.y)) * acc[mt][nt][1];
                float h2 = t1.x / (1.f + __expf(-t1.x)) * acc[mt][nt][2];
                float h3 = t1.y / (1.f + __expf(-t1.y)) * acc[mt][nt][3];
                *(uint32_t*)(Hh + o0) = pkh(__float2half_rn(h0), __float2half_rn(h1));
                *(uint32_t*)(Hh + o1) = pkh(__float2half_rn(h2), __float2half_rn(h3));
            }
        }
}

// ---------------- combine ----------------------------------------------------
__global__ void k_combine(float* __restrict__ out, int out_size) {
    int s = blockIdx.x;
    int sl1 = g_slot1[s], sl2 = g_slot2[s];
    float g1 = (sl1 >= 0) ? g_g1[s] : 0.f;
    float g2 = (sl2 >= 0) ? g_g2[s] : 0.f;
    float dn = fmaxf(g1 + g2, 1e-9f);
    g1 /= dn; g2 /= dn;
    const float4* r1 = (sl1 >= 0)
        ? (const float4*)(g_eo + ((size_t)g_idx1[s] * CAP + sl1) * DIM) : nullptr;
    const float4* r2 = (sl2 >= 0)
        ? (const float4*)(g_eo + ((size_t)g_idx2[s] * CAP + sl2) * DIM) : nullptr;
    float4* o = (float4*)(out + (size_t)s * DIM);
    for (int j = threadIdx.x; j < DIM / 4; j += blockDim.x) {
        float4 v = make_float4(0.f, 0.f, 0.f, 0.f);
        if (r1) { float4 t = r1[j]; v.x += g1 * t.x; v.y += g1 * t.y; v.z += g1 * t.z; v.w += g1 * t.w; }
        if (r2) { float4 t = r2[j]; v.x += g2 * t.x; v.y += g2 * t.y; v.z += g2 * t.z; v.w += g2 * t.w; }
        o[j] = v;
    }
    if (s == 0) {
        size_t base = (size_t)S_TOK * DIM;
        if ((size_t)out_size > base && threadIdx.x == 0) out[base] = g_laux;
        if ((size_t)out_size >= base + 1 + NE && threadIdx.x >= 1 && threadIdx.x <= NE)
            out[base + threadIdx.x] = (float)g_count1[threadIdx.x - 1];
    }
}

// ---------------- launch -----------------------------------------------------
extern "C" void kernel_launch(void* const* d_in, const int* in_sizes, int n_in,
                              void* d_out, int out_size) {
    (void)in_sizes; (void)n_in;
    const float* x  = (const float*)d_in[0];
    const float* wg = (const float*)d_in[1];
    const float* w1 = (const float*)d_in[2];
    const float* w3 = (const float*)d_in[3];
    const float* w2 = (const float*)d_in[4];
    float* out = (float*)d_out;

    cudaFuncSetAttribute(k_gemm_f<0>, cudaFuncAttributeMaxDynamicSharedMemorySize, GSMEM);
    cudaFuncSetAttribute(k_gemm_f<1>, cudaFuncAttributeMaxDynamicSharedMemorySize, GSMEM);

    void *p_ah, *p_w1h, *p_w3h, *p_w2h, *p_t1, *p_hh, *p_eo;
    cudaGetSymbolAddress(&p_ah, g_ah);
    cudaGetSymbolAddress(&p_w1h, g_w1h); cudaGetSymbolAddress(&p_w3h, g_w3h);
    cudaGetSymbolAddress(&p_w2h, g_w2h); cudaGetSymbolAddress(&p_t1, g_t1);
    cudaGetSymbolAddress(&p_hh, g_hh);   cudaGetSymbolAddress(&p_eo, g_eo);

    k_init<<<(NE * CAP + 255) / 256, 256>>>();
    k_logits<<<S_TOK, 128>>>(x, wg);
    k_top2<<<S_TOK / 256, 256>>>();
    k_scan<<<1, 256>>>();
    k_dispatch_h<<<NE * CAP, 256>>>(x);

    const size_t NW4 = (size_t)NE * DIM * FF / 4;
    int wgrid = (int)((NW4 + 255) / 256);
    k_wcvt<<<wgrid, 256>>>((const float4*)w1, (uint2*)p_w1h, NW4);
    k_wcvt<<<wgrid, 256>>>((const float4*)w3, (uint2*)p_w3h, NW4);
    k_wcvt<<<wgrid, 256>>>((const float4*)w2, (uint2*)p_w2h, NW4);

    dim3 grid1(FF / 128, CAP / 128, NE);   // (43, 8, 8)
    // t1 = xe @ w1 (fp32)
    k_gemm_f<0><<<grid1, 256, GSMEM>>>((const fp16*)p_ah, (const fp16*)p_w1h,
                                       (float*)p_t1, nullptr, nullptr, FF, DIM);
    // h = silu(t1) * (xe @ w3)  -> fp16 hh (fused epilogue)
    k_gemm_f<1><<<grid1, 256, GSMEM>>>((const fp16*)p_ah, (const fp16*)p_w3h,
                                       nullptr, (const float*)p_t1,
                                       (fp16*)p_hh, FF, DIM);
    dim3 grid2(DIM / 128, CAP / 128, NE);  // (16, 8, 8)
    k_gemm_f<0><<<grid2, 256, GSMEM>>>((const fp16*)p_hh, (const fp16*)p_w2h,
                                       (float*)p_eo, nullptr, nullptr, DIM, FF);

    k_combine<<<S_TOK, 256>>>(out, out_size);
}